// round 15
// baseline (speedup 1.0000x reference)
#include <cuda_runtime.h>
#include <cuda_bf16.h>
#include <cstdint>
#include <cstddef>

// Problem dims
#define BB  128
#define SS  256
#define DD  64
#define HH  512
#define H2V 1024
#define GEV 2048
#define GDV 4096
#define TT  60
#define BSV (BB*SS)      // 32768
#define BHV (BB*HH)      // 65536
#define BH2 (BB*H2V)     // 131072

// ---------------- scratch (device globals; no allocation allowed) -------------
__device__ float g_xg  [2*BSV*GEV];   // gate preactivations [dir][b][s][g]
__device__ float g_h0  [BSV*H2V];     // encoder layer0 output
__device__ float g_enc [BSV*H2V];     // encoder layer1 output
__device__ float g_ec  [2*BHV];       // enc c [dir][b][h]
__device__ float g_dh  [6*BH2];       // dec h fp32 ping-pong [cell][parity][b][h2]
__device__ float g_dc  [3*BH2];       // dec c
__device__ float g_gates[2*BB*GDV];   // partial gates for cells 2,3
__device__ float g_q   [3*BH2];       // attention queries q = W^T h [head][b][1024]

// bf16 split buffers (wbf reused: enc Wih splits early, then WT splits)
__device__ __nv_bfloat16 g_abf_hi[BSV*H2V];
__device__ __nv_bfloat16 g_abf_lo[BSV*H2V];
__device__ __nv_bfloat16 g_wbf_hi[2*GEV*H2V];
__device__ __nv_bfloat16 g_wbf_lo[2*GEV*H2V];

// recurrent weights pre-split (hi/lo)
#define OFF_E0   0ull
#define OFF_E1   2097152ull
#define OFF_D1I  4194304ull
#define OFF_D2I  8650752ull
#define OFF_D3I  17039360ull
#define OFF_D1H  25427968ull
#define OFF_D2H  29622272ull
#define OFF_D3H  33816576ull
#define RW_TOT   38010880ull
__device__ __nv_bfloat16 g_rwh[RW_TOT];
__device__ __nv_bfloat16 g_rwl[RW_TOT];

// recurrent activations bf16 hi/lo
__device__ __nv_bfloat16 g_ehbh[2*2*BHV];   // enc h [par][dir][b][512]
__device__ __nv_bfloat16 g_ehbl[2*2*BHV];
__device__ __nv_bfloat16 g_dhbh[3*2*BH2];   // dec h [cell][par][b][1024]
__device__ __nv_bfloat16 g_dhbl[3*2*BH2];
__device__ __nv_bfloat16 g_cxh [3*BH2];     // ctx [head][b][1024]
__device__ __nv_bfloat16 g_cxl [3*BH2];
__device__ __nv_bfloat16 g_pvh [BB*DD];     // prev y bf16
__device__ __nv_bfloat16 g_pvl [BB*DD];

__device__ __forceinline__ float sigf(float x) { return 1.0f / (1.0f + expf(-x)); }

__device__ __forceinline__ uint32_t smem_u32(const void* p) {
    uint32_t a;
    asm("{ .reg .u64 t; cvta.to.shared.u64 t, %1; cvt.u32.u64 %0, t; }" : "=r"(a) : "l"(p));
    return a;
}

#define MMA4(d, a, b0v, b1v) \
    asm volatile( \
        "mma.sync.aligned.m16n8k16.row.col.f32.bf16.bf16.f32 " \
        "{%0,%1,%2,%3},{%4,%5,%6,%7},{%8,%9},{%0,%1,%2,%3};" \
        : "+f"((d)[0]), "+f"((d)[1]), "+f"((d)[2]), "+f"((d)[3]) \
        : "r"((a)[0]), "r"((a)[1]), "r"((a)[2]), "r"((a)[3]), "r"(b0v), "r"(b1v))

#define LDSM4(r, addr) \
    asm volatile("ldmatrix.sync.aligned.m8n8.x4.shared.b16 {%0,%1,%2,%3},[%4];" \
        : "=r"((r)[0]), "=r"((r)[1]), "=r"((r)[2]), "=r"((r)[3]) : "r"(addr))

#define LDSM4B(r0, r1, r2, r3, addr) \
    asm volatile("ldmatrix.sync.aligned.m8n8.x4.shared.b16 {%0,%1,%2,%3},[%4];" \
        : "=r"(r0), "=r"(r1), "=r"(r2), "=r"(r3) : "r"(addr))

// =====================  batch HMMA bf16-split GEMM (verified R5) =============
#define G_TILE_B 10240
#define G_STG    (4 * G_TILE_B)
#define G_DSM    (2 * G_STG + 128)

__device__ __forceinline__ void gemm_body(
    const __nv_bfloat16* __restrict__ Ahi, const __nv_bfloat16* __restrict__ Alo,
    const __nv_bfloat16* __restrict__ Whi, const __nv_bfloat16* __restrict__ Wlo,
    const float* __restrict__ bias, float* __restrict__ C, int N, int K,
    int bm, int bn, char* dsm)
{
    const int tid = threadIdx.x, lane = tid & 31, wid = tid >> 5;
    const int wr = wid >> 1, wc = wid & 1;
    const uint32_t sbase = (smem_u32(dsm) + 127u) & ~127u;
    const int nch = K >> 5;

    float acc[2][8][4];
#pragma unroll
    for (int mi = 0; mi < 2; mi++)
#pragma unroll
        for (int ni = 0; ni < 8; ni++)
#pragma unroll
            for (int q = 0; q < 4; q++) acc[mi][ni][q] = 0.0f;

    auto load = [&](int c, int st) {
#pragma unroll
        for (int q = 0; q < 8; q++) {
            int id = q * 256 + tid;
            int t  = id >> 9;
            int r  = (id >> 2) & 127;
            int sg = id & 3;
            const __nv_bfloat16* basep = (t == 0 ? Ahi : t == 1 ? Alo : t == 2 ? Whi : Wlo);
            int grow = (t < 2 ? bm : bn) + r;
            const __nv_bfloat16* src = basep + (size_t)grow * K + c * 32 + sg * 8;
            uint32_t dst = sbase + st * G_STG + t * G_TILE_B + r * 80 + sg * 16;
            asm volatile("cp.async.cg.shared.global [%0], [%1], 16;" :: "r"(dst), "l"(src));
        }
        asm volatile("cp.async.commit_group;" ::: "memory");
    };

    load(0, 0);

    for (int c = 0; c < nch; c++) {
        if (c + 1 < nch) {
            load(c + 1, (c + 1) & 1);
            asm volatile("cp.async.wait_group 1;" ::: "memory");
        } else {
            asm volatile("cp.async.wait_group 0;" ::: "memory");
        }
        __syncthreads();

        const uint32_t stb = sbase + (c & 1) * G_STG;
        const uint32_t aB[2] = { stb, stb + G_TILE_B };
        const uint32_t wB[2] = { stb + 2 * G_TILE_B, stb + 3 * G_TILE_B };
        const int arow = wr * 32 + (lane & 15);
        const int wrow = wc * 64 + (lane & 15);
        const int cc   = (lane >> 4) * 16;

#pragma unroll
        for (int ks = 0; ks < 2; ks++) {
            uint32_t afr[2][2][4];
#pragma unroll
            for (int s = 0; s < 2; s++)
#pragma unroll
                for (int mi = 0; mi < 2; mi++) {
                    uint32_t ad = aB[s] + (uint32_t)(arow + mi * 16) * 80 + ks * 32 + cc;
                    LDSM4(afr[s][mi], ad);
                }
#pragma unroll
            for (int wsp = 0; wsp < 2; wsp++) {
#pragma unroll
                for (int nb = 0; nb < 4; nb++) {
                    uint32_t r0, r1, r2, r3;
                    uint32_t bd = wB[wsp] + (uint32_t)(wrow + nb * 16) * 80 + ks * 32 + cc;
                    LDSM4B(r0, r1, r2, r3, bd);
#pragma unroll
                    for (int mi = 0; mi < 2; mi++) {
                        MMA4(acc[mi][nb * 2],     afr[0][mi], r0, r2);
                        MMA4(acc[mi][nb * 2 + 1], afr[0][mi], r1, r3);
                        if (wsp == 0) {
                            MMA4(acc[mi][nb * 2],     afr[1][mi], r0, r2);
                            MMA4(acc[mi][nb * 2 + 1], afr[1][mi], r1, r3);
                        }
                    }
                }
            }
        }
        __syncthreads();
    }

#pragma unroll
    for (int mi = 0; mi < 2; mi++) {
#pragma unroll
        for (int ni = 0; ni < 8; ni++) {
            int r0 = bm + wr * 32 + mi * 16 + (lane >> 2);
            int c0 = bn + wc * 64 + ni * 8 + (lane & 3) * 2;
            float b0v = bias ? bias[c0] : 0.0f;
            float b1v = bias ? bias[c0 + 1] : 0.0f;
            float2 v0 = { acc[mi][ni][0] + b0v, acc[mi][ni][1] + b1v };
            float2 v1 = { acc[mi][ni][2] + b0v, acc[mi][ni][3] + b1v };
            *(float2*)&C[(size_t)r0 * N + c0]       = v0;
            *(float2*)&C[(size_t)(r0 + 8) * N + c0] = v1;
        }
    }
}

__global__ __launch_bounds__(256) void gemm_mma(
    const __nv_bfloat16* __restrict__ Ahi, const __nv_bfloat16* __restrict__ Alo,
    const __nv_bfloat16* __restrict__ Whi, const __nv_bfloat16* __restrict__ Wlo,
    const float* __restrict__ bias, float* __restrict__ C, int N, int K)
{
    extern __shared__ char dsm[];
    gemm_body(Ahi, Alo, Whi, Wlo, bias, C, N, K, blockIdx.y * 128, blockIdx.x * 128, dsm);
}

// q[head] = h[head] @ WT[head]  (blockIdx.y < 3)
// blockIdx.y == 3: fold previous step's out_proj (y_{t-1} = h3 @ outW^T + b,
// plus bf16 prev feedback). do_y==0 skips (step 0).
__global__ __launch_bounds__(256) void qgemm_mma(
    const __nv_bfloat16* __restrict__ hbh, const __nv_bfloat16* __restrict__ hbl,
    const __nv_bfloat16* __restrict__ wth, const __nv_bfloat16* __restrict__ wtl,
    float* __restrict__ q,
    const float* __restrict__ h3,      // [B][1024] fp32 (same parity as hbh)
    const float* __restrict__ outW,    // [64][1024]
    const float* __restrict__ outb,    // [64]
    float* __restrict__ y,             // [B][T][64]
    __nv_bfloat16* __restrict__ pvh, __nv_bfloat16* __restrict__ pvl,
    int tprev, int do_y)
{
    extern __shared__ char dsm[];
    if (blockIdx.y < 3) {
        const int head = blockIdx.y;
        const size_t cs = (size_t)2 * BH2;
        gemm_body(hbh + (size_t)head * cs, hbl + (size_t)head * cs,
                  wth + (size_t)head * H2V * H2V, wtl + (size_t)head * H2V * H2V,
                  nullptr, q + (size_t)head * BH2, H2V, H2V,
                  0, blockIdx.x * 128, dsm);
        return;
    }
    // ---- y-block: 8 blocks x 16 batch rows ----
    if (!do_y) return;
    float* sh = (float*)dsm;               // [16][1024] = 64KB (G_DSM = 82KB)
    const int tid = threadIdx.x;
    const int b0 = blockIdx.x * 16;
    for (int i = tid; i < 16 * 1024; i += 256)
        sh[i] = h3[(size_t)(b0 + (i >> 10)) * H2V + (i & 1023)];
    __syncthreads();
    const int d = tid & 63, bq = tid >> 6;    // 4 threads groups x 64 d
    const float* wr = outW + (size_t)d * H2V;
#pragma unroll
    for (int bi = 0; bi < 4; bi++) {
        int bl = bq * 4 + bi;
        const float* hr = &sh[bl * 1024];
        float acc = outb[d];
        for (int k = 0; k < H2V; k += 4) {
            float4 wv = *(const float4*)(wr + k);
            acc += wv.x * hr[k] + wv.y * hr[k + 1] + wv.z * hr[k + 2] + wv.w * hr[k + 3];
        }
        int b = b0 + bl;
        y[((size_t)b * TT + tprev) * DD + d] = acc;
        __nv_bfloat16 hb = __float2bfloat16(acc);
        pvh[b * DD + d] = hb;
        pvl[b * DD + d] = __float2bfloat16(acc - __bfloat162float(hb));
    }
}

// fp32 -> bf16 hi/lo split
__global__ void split_bf16(const float* __restrict__ s, __nv_bfloat16* __restrict__ hi,
                           __nv_bfloat16* __restrict__ lo, long n)
{
    long stride = (long)gridDim.x * blockDim.x;
    for (long i = blockIdx.x * (long)blockDim.x + threadIdx.x; i < n; i += stride) {
        float v = s[i];
        __nv_bfloat16 h = __float2bfloat16(v);
        hi[i] = h;
        lo[i] = __float2bfloat16(v - __bfloat162float(h));
    }
}

// transpose + split: WT[e][d] = W[d][e], 1024x1024, bf16 hi/lo
__global__ __launch_bounds__(256) void transpose_split(
    const float* __restrict__ W, __nv_bfloat16* __restrict__ hi, __nv_bfloat16* __restrict__ lo)
{
    __shared__ float tile[32][33];
    const int bx = blockIdx.x * 32, by = blockIdx.y * 32;
    const int tx = threadIdx.x & 31, ty = threadIdx.x >> 5;
#pragma unroll
    for (int i = 0; i < 32; i += 8)
        tile[ty + i][tx] = W[(size_t)(bx + ty + i) * H2V + by + tx];
    __syncthreads();
#pragma unroll
    for (int i = 0; i < 32; i += 8) {
        float v = tile[tx][ty + i];
        size_t idx = (size_t)(by + ty + i) * H2V + bx + tx;
        __nv_bfloat16 h = __float2bfloat16(v);
        hi[idx] = h;
        lo[idx] = __float2bfloat16(v - __bfloat162float(h));
    }
}

// =====================  HMMA recurrent cell machinery ========================
// Block tile M=128 (batch) x N=32 (4 gates x 8 units); 8 warps of 16x32.
// K chunks of 64. 144B rows (conflict-free ldmatrix).
#define RC_ATILE 18432                 // 128*144
#define RC_WOFF  36864                 // 2*RC_ATILE
#define RC_WTILE 4608                  // 32*144
#define RC_STG   46080
// decoder kernels: 2-stage (2 CTAs/SM at 109.5KB)
#define RC_GS_OFF (2 * RC_STG)         // 92160
#define RC_DSM   (RC_GS_OFF + 128 * 34 * 4)   // 109568
// encoder kernel: 3-stage (R13 proven)
#define E3_GS_OFF (3 * RC_STG)         // 138240
#define E3_DSM   (E3_GS_OFF + 128 * 34 * 4)   // 155648

struct Seg {
    const __nv_bfloat16 *Ah, *Al, *Wh, *Wl;
    int lda, ldw, nch;   // nch in 64-wide chunks
};

__device__ __forceinline__ void rc_load64(const Seg& s, int kc, uint32_t stb,
                                          int tid, int ubase, int GST)
{
#pragma unroll
    for (int q = 0; q < 10; q++) {
        int id = q * 256 + tid;      // 0..2559
        uint32_t dst; const __nv_bfloat16* src;
        if (id < 2048) {             // A: 2 tiles x 128 rows x 8 segs
            int t = id >> 10, r = (id >> 3) & 127, sg = id & 7;
            src = (t ? s.Al : s.Ah) + (size_t)r * s.lda + kc + sg * 8;
            dst = stb + t * RC_ATILE + r * 144 + sg * 16;
        } else {                     // W: 2 tiles x 32 rows x 8 segs
            int id2 = id - 2048;     // 0..511
            int t = id2 >> 8, r = (id2 >> 3) & 31, sg = id2 & 7;
            int grow = (r >> 3) * GST + ubase + (r & 7);
            src = (t ? s.Wl : s.Wh) + (size_t)grow * s.ldw + kc + sg * 8;
            dst = stb + RC_WOFF + t * RC_WTILE + r * 144 + sg * 16;
        }
        asm volatile("cp.async.cg.shared.global [%0], [%1], 16;" :: "r"(dst), "l"(src));
    }
    asm volatile("cp.async.commit_group;" ::: "memory");
}

__device__ __forceinline__ void rc_consume64(uint32_t stb, int wid, int lane,
                                             float (*acc)[4])
{
    const uint32_t cc   = (lane >> 4) * 16;
    const uint32_t arow = wid * 16 + (lane & 15);
    const uint32_t wrow = (lane & 15);
#pragma unroll
    for (int ks = 0; ks < 4; ks++) {
        uint32_t ah[4], al[4];
        LDSM4(ah, stb + arow * 144 + ks * 32 + cc);
        LDSM4(al, stb + RC_ATILE + arow * 144 + ks * 32 + cc);
        uint32_t b0,b1,b2,b3,b4,b5,b6,b7;
        LDSM4B(b0,b1,b2,b3, stb + RC_WOFF + wrow * 144 + ks * 32 + cc);
        LDSM4B(b4,b5,b6,b7, stb + RC_WOFF + (wrow + 16) * 144 + ks * 32 + cc);
        uint32_t l0,l1,l2,l3,l4,l5,l6,l7;
        LDSM4B(l0,l1,l2,l3, stb + RC_WOFF + RC_WTILE + wrow * 144 + ks * 32 + cc);
        LDSM4B(l4,l5,l6,l7, stb + RC_WOFF + RC_WTILE + (wrow + 16) * 144 + ks * 32 + cc);
        MMA4(acc[0], ah, b0, b2); MMA4(acc[0], al, b0, b2); MMA4(acc[0], ah, l0, l2);
        MMA4(acc[1], ah, b1, b3); MMA4(acc[1], al, b1, b3); MMA4(acc[1], ah, l1, l3);
        MMA4(acc[2], ah, b4, b6); MMA4(acc[2], al, b4, b6); MMA4(acc[2], ah, l4, l6);
        MMA4(acc[3], ah, b5, b7); MMA4(acc[3], al, b5, b7); MMA4(acc[3], ah, l5, l7);
    }
}

__device__ __forceinline__ void rc_epilogue_to_smem(float (*gs)[34], float (*acc)[4],
                                                    int wid, int lane)
{
#pragma unroll
    for (int nt = 0; nt < 4; nt++) {
        int r0 = wid * 16 + (lane >> 2);
        int c0 = nt * 8 + (lane & 3) * 2;
        gs[r0][c0]     = acc[nt][0];
        gs[r0][c0 + 1] = acc[nt][1];
        gs[r0 + 8][c0]     = acc[nt][2];
        gs[r0 + 8][c0 + 1] = acc[nt][3];
    }
}

// 2-stage pipeline driver over a segment list (decoder)
__device__ __forceinline__ void rc_run(const Seg* segs, int total, uint32_t sb,
                                       int tid, int wid, int lane, int ubase, int GST,
                                       float (*acc)[4])
{
    int si = 0, kc = 0;
    rc_load64(segs[0], 0, sb, tid, ubase, GST);
    for (int ci = 0; ci < total; ci++) {
        int nsi = si, nkc = kc + 64;
        if (nkc >= segs[nsi].nch * 64) { nsi++; nkc = 0; }
        if (ci + 1 < total) {
            rc_load64(segs[nsi], nkc, sb + ((ci + 1) & 1) * RC_STG, tid, ubase, GST);
            asm volatile("cp.async.wait_group 1;" ::: "memory");
        } else {
            asm volatile("cp.async.wait_group 0;" ::: "memory");
        }
        __syncthreads();
        rc_consume64(sb + (ci & 1) * RC_STG, wid, lane, acc);
        __syncthreads();
        si = nsi; kc = nkc;
    }
}

// ---------------- encoder recurrent step (HMMA, 3-stage pipeline) -------------
__global__ __launch_bounds__(256) void enc_step_mma(
    const __nv_bfloat16* __restrict__ hh, const __nv_bfloat16* __restrict__ hl,
    const __nv_bfloat16* __restrict__ Wh, const __nv_bfloat16* __restrict__ Wl,
    const float* __restrict__ xg, float* __restrict__ cst,
    __nv_bfloat16* __restrict__ hho, __nv_bfloat16* __restrict__ hlo,
    float* __restrict__ hs, int t)
{
    extern __shared__ char dsm[];
    const int tid = threadIdx.x, lane = tid & 31, wid = tid >> 5;
    const int dir = blockIdx.y, ubase = blockIdx.x * 8;
    const int td = dir ? (SS - 1 - t) : t;
    const uint32_t sb = smem_u32(dsm);
    float (*gs)[34] = (float (*)[34])(dsm + E3_GS_OFF);

    Seg s = { hh + (size_t)dir * BHV, hl + (size_t)dir * BHV,
              Wh + (size_t)dir * GEV * HH, Wl + (size_t)dir * GEV * HH,
              HH, HH, 8 };

    float acc[4][4];
#pragma unroll
    for (int nt = 0; nt < 4; nt++)
#pragma unroll
        for (int q = 0; q < 4; q++) acc[nt][q] = 0.0f;

    // 3-stage: two loads always in flight
    rc_load64(s, 0, sb, tid, ubase, HH);
    rc_load64(s, 64, sb + RC_STG, tid, ubase, HH);
    for (int ci = 0; ci < 8; ci++) {
        if (ci + 2 < 8)
            rc_load64(s, (ci + 2) * 64, sb + ((ci + 2) % 3) * RC_STG, tid, ubase, HH);
        int inflight = 7 - ci; if (inflight > 2) inflight = 2;
        if (inflight >= 2)      asm volatile("cp.async.wait_group 2;" ::: "memory");
        else if (inflight == 1) asm volatile("cp.async.wait_group 1;" ::: "memory");
        else                    asm volatile("cp.async.wait_group 0;" ::: "memory");
        __syncthreads();
        rc_consume64(sb + (ci % 3) * RC_STG, wid, lane, acc);
        __syncthreads();
    }

    rc_epilogue_to_smem(gs, acc, wid, lane);
    __syncthreads();

    const float* xgp = xg + (size_t)dir * BSV * GEV;
    float* cp = cst + (size_t)dir * BHV;
#pragma unroll
    for (int k = 0; k < 4; k++) {
        int idx = k * 256 + tid;
        int b = idx >> 3, u = idx & 7;
        int uu = ubase + u;
        size_t xrow = ((size_t)b * SS + td) * GEV;
        float gi = gs[b][u]      + xgp[xrow + uu];
        float gf = gs[b][8 + u]  + xgp[xrow + 512 + uu];
        float gg = gs[b][16 + u] + xgp[xrow + 1024 + uu];
        float go = gs[b][24 + u] + xgp[xrow + 1536 + uu];
        int hidx = b * HH + uu;
        float c = sigf(gf) * cp[hidx] + sigf(gi) * tanhf(gg);
        float h = sigf(go) * tanhf(c);
        cp[hidx] = c;
        hs[((size_t)b * SS + td) * H2V + dir * HH + uu] = h;
        __nv_bfloat16 hb = __float2bfloat16(h);
        hho[(size_t)dir * BHV + hidx] = hb;
        hlo[(size_t)dir * BHV + hidx] = __float2bfloat16(h - __bfloat162float(hb));
    }
}

// ---------------- decoder: parallel pre-pass (cell1 full + cells 2,3 partial) -
__global__ __launch_bounds__(256) void dec_pre(
    const __nv_bfloat16* __restrict__ cxh, const __nv_bfloat16* __restrict__ cxl,
    const __nv_bfloat16* __restrict__ pvh, const __nv_bfloat16* __restrict__ pvl,
    const __nv_bfloat16* __restrict__ hph, const __nv_bfloat16* __restrict__ hpl,
    const __nv_bfloat16* __restrict__ rwh, const __nv_bfloat16* __restrict__ rwl,
    const float* __restrict__ b1, const float* __restrict__ b2, const float* __restrict__ b3,
    float* __restrict__ cst1, float* __restrict__ h1fo,
    __nv_bfloat16* __restrict__ h1ho, __nv_bfloat16* __restrict__ h1lo,
    float* __restrict__ gates)
{
    extern __shared__ char dsm[];
    const int tid = threadIdx.x, lane = tid & 31, wid = tid >> 5;
    const int ubase = blockIdx.x * 8;
    const int c = blockIdx.y;
    const uint32_t sb = smem_u32(dsm);
    float (*gs)[34] = (float (*)[34])(dsm + RC_GS_OFF);
    const size_t cs = (size_t)2 * BH2;

    const unsigned long long offI = c == 0 ? OFF_D1I : (c == 1 ? OFF_D2I : OFF_D3I);
    const unsigned long long offH = c == 0 ? OFF_D1H : (c == 1 ? OFF_D2H : OFF_D3H);
    const int ldih = c == 0 ? (H2V + DD) : (2 * H2V);
    const float* bias = c == 0 ? b1 : (c == 1 ? b2 : b3);

    Seg segs[3];
    int total;
    segs[0] = { cxh + (size_t)c * BH2, cxl + (size_t)c * BH2,
                rwh + offI, rwl + offI, H2V, ldih, 16 };
    if (c == 0) {
        segs[1] = { pvh, pvl, rwh + offI + H2V, rwl + offI + H2V, DD, ldih, 1 };
        segs[2] = { hph, hpl, rwh + offH, rwl + offH, H2V, H2V, 16 };
        total = 33;
    } else {
        segs[1] = { hph + (size_t)c * cs, hpl + (size_t)c * cs,
                    rwh + offH, rwl + offH, H2V, H2V, 16 };
        total = 32;
    }

    float acc[4][4];
#pragma unroll
    for (int nt = 0; nt < 4; nt++)
#pragma unroll
        for (int q = 0; q < 4; q++) acc[nt][q] = 0.0f;

    rc_run(segs, total, sb, tid, wid, lane, ubase, H2V, acc);

    rc_epilogue_to_smem(gs, acc, wid, lane);
    __syncthreads();

    if (c == 0) {
#pragma unroll
        for (int k = 0; k < 4; k++) {
            int idx = k * 256 + tid;
            int b = idx >> 3, u = idx & 7;
            int uu = ubase + u;
            float gi = gs[b][u]      + bias[uu];
            float gf = gs[b][8 + u]  + bias[1024 + uu];
            float gg = gs[b][16 + u] + bias[2048 + uu];
            float go = gs[b][24 + u] + bias[3072 + uu];
            int hidx = b * H2V + uu;
            float cc = sigf(gf) * cst1[hidx] + sigf(gi) * tanhf(gg);
            float h = sigf(go) * tanhf(cc);
            cst1[hidx] = cc;
            h1fo[hidx] = h;
            __nv_bfloat16 hb = __float2bfloat16(h);
            h1ho[hidx] = hb;
            h1lo[hidx] = __float2bfloat16(h - __bfloat162float(hb));
        }
    } else {
        float* gp = gates + (size_t)(c - 1) * BB * GDV;
#pragma unroll
        for (int k = 0; k < 4; k++) {
            int idx = k * 256 + tid;
            int b = idx >> 3, u = idx & 7;
            int uu = ubase + u;
            gp[(size_t)b * GDV + uu]        = gs[b][u]      + bias[uu];
            gp[(size_t)b * GDV + 1024 + uu] = gs[b][8 + u]  + bias[1024 + uu];
            gp[(size_t)b * GDV + 2048 + uu] = gs[b][16 + u] + bias[2048 + uu];
            gp[(size_t)b * GDV + 3072 + uu] = gs[b][24 + u] + bias[3072 + uu];
        }
    }
}

// ---------------- decoder: finish cell (adds fresh-h term, pointwise) ---------
__global__ __launch_bounds__(256) void dec_fin(
    const __nv_bfloat16* __restrict__ ih, const __nv_bfloat16* __restrict__ il,
    const __nv_bfloat16* __restrict__ Wh, const __nv_bfloat16* __restrict__ Wl,
    int ldw,
    const float* __restrict__ gpart,
    float* __restrict__ cst, float* __restrict__ hfo,
    __nv_bfloat16* __restrict__ hho, __nv_bfloat16* __restrict__ hlo)
{
    extern __shared__ char dsm[];
    const int tid = threadIdx.x, lane = tid & 31, wid = tid >> 5;
    const int ubase = blockIdx.x * 8;
    const uint32_t sb = smem_u32(dsm);
    float (*gs)[34] = (float (*)[34])(dsm + RC_GS_OFF);

    Seg s = { ih, il, Wh, Wl, H2V, ldw, 16 };

    float acc[4][4];
#pragma unroll
    for (int nt = 0; nt < 4; nt++)
#pragma unroll
        for (int q = 0; q < 4; q++) acc[nt][q] = 0.0f;

    rc_run(&s, 16, sb, tid, wid, lane, ubase, H2V, acc);

    rc_epilogue_to_smem(gs, acc, wid, lane);
    __syncthreads();

#pragma unroll
    for (int k = 0; k < 4; k++) {
        int idx = k * 256 + tid;
        int b = idx >> 3, u = idx & 7;
        int uu = ubase + u;
        const float* gp = gpart + (size_t)b * GDV;
        float gi = gs[b][u]      + gp[uu];
        float gf = gs[b][8 + u]  + gp[1024 + uu];
        float gg = gs[b][16 + u] + gp[2048 + uu];
        float go = gs[b][24 + u] + gp[3072 + uu];
        int hidx = b * H2V + uu;
        float cc = sigf(gf) * cst[hidx] + sigf(gi) * tanhf(gg);
        float h = sigf(go) * tanhf(cc);
        cst[hidx] = cc;
        hfo[hidx] = h;
        __nv_bfloat16 hb = __float2bfloat16(h);
        hho[hidx] = hb;
        hlo[hidx] = __float2bfloat16(h - __bfloat162float(hb));
    }
}

// ---------------- q-based fused 3-head attention (R13 proven) -----------------
__global__ __launch_bounds__(256) void attend2(
    const float* __restrict__ dh,
    const float* __restrict__ q,
    const float* __restrict__ ab0, const float* __restrict__ ab1, const float* __restrict__ ab2,
    const float* __restrict__ enc,
    __nv_bfloat16* __restrict__ cxh, __nv_bfloat16* __restrict__ cxl)
{
    const int b = blockIdx.x, tid = threadIdx.x, lane = tid & 31, wid = tid >> 5;
    __shared__ float sa[3][SS];
    __shared__ float red[8];
    __shared__ float shb[3];
    __shared__ float redm[3][8];
    __shared__ float reds[3][8];

    const float* abp[3] = { ab0, ab1, ab2 };
#pragma unroll
    for (int hd = 0; hd < 3; hd++) {
        const float* hp = dh + (size_t)hd * 2 * BH2 + (size_t)b * H2V;
        const float* bp = abp[hd];
        float p = 0.0f;
        for (int d = tid; d < H2V; d += 256) p += hp[d] * bp[d];
#pragma unroll
        for (int off = 16; off; off >>= 1)
            p += __shfl_xor_sync(0xffffffffu, p, off);
        if (lane == 0) red[wid] = p;
        __syncthreads();
        if (tid == 0) {
            float s = 0.0f;
#pragma unroll
            for (int i = 0; i < 8; i++) s += red[i];
            shb[hd] = s;
        }
        __syncthreads();
    }

    float4 qr[3][8];
#pragma unroll
    for (int hd = 0; hd < 3; hd++)
#pragma unroll
        for (int k = 0; k < 8; k++)
            qr[hd][k] = *(const float4*)&q[(size_t)hd * BH2 + (size_t)b * H2V + k * 128 + lane * 4];

    const float* eb = enc + (size_t)b * SS * H2V;
    for (int s = wid * 32; s < wid * 32 + 32; s++) {
        const float* er = eb + (size_t)s * H2V + lane * 4;
        float a0 = 0.0f, a1 = 0.0f, a2 = 0.0f;
#pragma unroll
        for (int k = 0; k < 8; k++) {
            float4 ev = *(const float4*)(er + k * 128);
            a0 += ev.x * qr[0][k].x + ev.y * qr[0][k].y + ev.z * qr[0][k].z + ev.w * qr[0][k].w;
            a1 += ev.x * qr[1][k].x + ev.y * qr[1][k].y + ev.z * qr[1][k].z + ev.w * qr[1][k].w;
            a2 += ev.x * qr[2][k].x + ev.y * qr[2][k].y + ev.z * qr[2][k].z + ev.w * qr[2][k].w;
        }
#pragma unroll
        for (int off = 16; off; off >>= 1) {
            a0 += __shfl_xor_sync(0xffffffffu, a0, off);
            a1 += __shfl_xor_sync(0xffffffffu, a1, off);
            a2 += __shfl_xor_sync(0xffffffffu, a2, off);
        }
        if (lane == 0) {
            sa[0][s] = a0 + shb[0];
            sa[1][s] = a1 + shb[1];
            sa[2][s] = a2 + shb[2];
        }
    }
    __syncthreads();

    float ev3[3];
#pragma unroll
    for (int hd = 0; hd < 3; hd++) {
        float m = sa[hd][tid];
#pragma unroll
        for (int off = 16; off; off >>= 1)
            m = fmaxf(m, __shfl_xor_sync(0xffffffffu, m, off));
        if (lane == 0) redm[hd][wid] = m;
    }
    __syncthreads();
#pragma unroll
    for (int hd = 0; hd < 3; hd++) {
        float m = redm[hd][0];
#pragma unroll
        for (int i = 1; i < 8; i++) m = fmaxf(m, redm[hd][i]);
        float e = expf(sa[hd][tid] - m);
        ev3[hd] = e;
        float ssum = e;
#pragma unroll
        for (int off = 16; off; off >>= 1)
            ssum += __shfl_xor_sync(0xffffffffu, ssum, off);
        if (lane == 0) reds[hd][wid] = ssum;
    }
    __syncthreads();
#pragma unroll
    for (int hd = 0; hd < 3; hd++) {
        float tot = reds[hd][0];
#pragma unroll
        for (int i = 1; i < 8; i++) tot += reds[hd][i];
        sa[hd][tid] = ev3[hd] / tot;
    }
    __syncthreads();

    float4 a0 = {0,0,0,0}, a1 = {0,0,0,0}, a2 = {0,0,0,0};
    const float* er = enc + (size_t)b * SS * H2V + tid * 4;
#pragma unroll 4
    for (int s = 0; s < SS; s++) {
        float4 ev4 = *(const float4*)(er + (size_t)s * H2V);
        float w0 = sa[0][s], w1 = sa[1][s], w2 = sa[2][s];
        a0.x += w0 * ev4.x; a0.y += w0 * ev4.y; a0.z += w0 * ev4.z; a0.w += w0 * ev4.w;
        a1.x += w1 * ev4.x; a1.y += w1 * ev4.y; a1.z += w1 * ev4.z; a1.w += w1 * ev4.w;
        a2.x += w2 * ev4.x; a2.y += w2 * ev4.y; a2.z += w2 * ev4.z; a2.w += w2 * ev4.w;
    }
#pragma unroll
    for (int hd = 0; hd < 3; hd++) {
        float4 v = hd == 0 ? a0 : hd == 1 ? a1 : a2;
        size_t base = (size_t)hd * BH2 + (size_t)b * H2V + tid * 4;
        float vv[4] = { v.x, v.y, v.z, v.w };
#pragma unroll
        for (int qd = 0; qd < 4; qd++) {
            __nv_bfloat16 hb = __float2bfloat16(vv[qd]);
            cxh[base + qd] = hb;
            cxl[base + qd] = __float2bfloat16(vv[qd] - __bfloat162float(hb));
        }
    }
}

// ---------------- output projection (final step only) --------------------------
__global__ __launch_bounds__(64) void out_proj(
    const float* __restrict__ h,
    const float* __restrict__ W,
    const float* __restrict__ bias,
    float* __restrict__ y,
    __nv_bfloat16* __restrict__ pvh, __nv_bfloat16* __restrict__ pvl,
    int t)
{
    const int b = blockIdx.x, d = threadIdx.x;
    __shared__ float sh[H2V];
    for (int i = d; i < H2V; i += 64) sh[i] = h[(size_t)b * H2V + i];
    __syncthreads();
    float acc = bias[d];
    const float* wr = W + (size_t)d * H2V;
    for (int k = 0; k < H2V; k += 4) {
        float4 wv = *(const float4*)(wr + k);
        acc += wv.x * sh[k] + wv.y * sh[k + 1] + wv.z * sh[k + 2] + wv.w * sh[k + 3];
    }
    y[((size_t)b * TT + t) * DD + d] = acc;
    __nv_bfloat16 hb = __float2bfloat16(acc);
    pvh[b * DD + d] = hb;
    pvl[b * DD + d] = __float2bfloat16(acc - __bfloat162float(hb));
}

__global__ void set_prev(const float* __restrict__ x,
                         __nv_bfloat16* __restrict__ pvh, __nv_bfloat16* __restrict__ pvl)
{
    int i = blockIdx.x * blockDim.x + threadIdx.x;
    if (i < BB * DD) {
        int b = i / DD, d = i % DD;
        float v = x[((size_t)b * SS + (SS - 1)) * DD + d];
        __nv_bfloat16 hb = __float2bfloat16(v);
        pvh[i] = hb;
        pvl[i] = __float2bfloat16(v - __bfloat162float(hb));
    }
}

// ---------------- host orchestration ------------------------------------------
extern "C" void kernel_launch(void* const* d_in, const int* in_sizes, int n_in,
                              void* d_out, int out_size)
{
    (void)in_sizes; (void)n_in; (void)out_size;
    const float* x        = (const float*)d_in[0];
    const float* enc0_Wih = (const float*)d_in[1];
    const float* enc0_Whh = (const float*)d_in[2];
    const float* enc0_b   = (const float*)d_in[3];
    const float* enc1_Wih = (const float*)d_in[4];
    const float* enc1_Whh = (const float*)d_in[5];
    const float* enc1_b   = (const float*)d_in[6];
    const float* attnW[3] = {(const float*)d_in[7],  (const float*)d_in[9],  (const float*)d_in[11]};
    const float* attnb[3] = {(const float*)d_in[8],  (const float*)d_in[10], (const float*)d_in[12]};
    const float* dec1_Wih = (const float*)d_in[13];
    const float* dec1_Whh = (const float*)d_in[14];
    const float* dec1_b   = (const float*)d_in[15];
    const float* dec2_Wih = (const float*)d_in[16];
    const float* dec2_Whh = (const float*)d_in[17];
    const float* dec2_b   = (const float*)d_in[18];
    const float* dec3_Wih = (const float*)d_in[19];
    const float* dec3_Whh = (const float*)d_in[20];
    const float* dec3_b   = (const float*)d_in[21];
    const float* out_W    = (const float*)d_in[22];
    const float* out_b    = (const float*)d_in[23];
    float* out = (float*)d_out;

    float *xg, *h0, *enc, *ec, *dh, *dcst, *gates, *q;
    __nv_bfloat16 *ah, *al, *wh, *wl, *rwh, *rwl;
    __nv_bfloat16 *ehbh, *ehbl, *dhbh, *dhbl, *cxh, *cxl, *pvh, *pvl;
    cudaGetSymbolAddress((void**)&xg,    g_xg);
    cudaGetSymbolAddress((void**)&h0,    g_h0);
    cudaGetSymbolAddress((void**)&enc,   g_enc);
    cudaGetSymbolAddress((void**)&ec,    g_ec);
    cudaGetSymbolAddress((void**)&dh,    g_dh);
    cudaGetSymbolAddress((void**)&dcst,  g_dc);
    cudaGetSymbolAddress((void**)&gates, g_gates);
    cudaGetSymbolAddress((void**)&q,     g_q);
    cudaGetSymbolAddress((void**)&ah,    g_abf_hi);
    cudaGetSymbolAddress((void**)&al,    g_abf_lo);
    cudaGetSymbolAddress((void**)&wh,    g_wbf_hi);
    cudaGetSymbolAddress((void**)&wl,    g_wbf_lo);
    cudaGetSymbolAddress((void**)&rwh,   g_rwh);
    cudaGetSymbolAddress((void**)&rwl,   g_rwl);
    cudaGetSymbolAddress((void**)&ehbh,  g_ehbh);
    cudaGetSymbolAddress((void**)&ehbl,  g_ehbl);
    cudaGetSymbolAddress((void**)&dhbh,  g_dhbh);
    cudaGetSymbolAddress((void**)&dhbl,  g_dhbl);
    cudaGetSymbolAddress((void**)&cxh,   g_cxh);
    cudaGetSymbolAddress((void**)&cxl,   g_cxl);
    cudaGetSymbolAddress((void**)&pvh,   g_pvh);
    cudaGetSymbolAddress((void**)&pvl,   g_pvl);

    cudaFuncSetAttribute(gemm_mma,     cudaFuncAttributeMaxDynamicSharedMemorySize, G_DSM);
    cudaFuncSetAttribute(qgemm_mma,    cudaFuncAttributeMaxDynamicSharedMemorySize, G_DSM);
    cudaFuncSetAttribute(enc_step_mma, cudaFuncAttributeMaxDynamicSharedMemorySize, E3_DSM);
    cudaFuncSetAttribute(dec_pre,      cudaFuncAttributeMaxDynamicSharedMemorySize, RC_DSM);
    cudaFuncSetAttribute(dec_fin,      cudaFuncAttributeMaxDynamicSharedMemorySize, RC_DSM);

    const size_t dirXG = (size_t)BSV * GEV;

    // ---- pre-split recurrent weights ----
    split_bf16<<<1024, 256>>>(enc0_Whh, rwh + OFF_E0,  rwl + OFF_E0,  2L * GEV * HH);
    split_bf16<<<1024, 256>>>(enc1_Whh, rwh + OFF_E1,  rwl + OFF_E1,  2L * GEV * HH);
    split_bf16<<<1024, 256>>>(dec1_Wih, rwh + OFF_D1I, rwl + OFF_D1I, (long)GDV * (H2V + DD));
    split_bf16<<<1024, 256>>>(dec2_Wih, rwh + OFF_D2I, rwl + OFF_D2I, (long)GDV * 2 * H2V);
    split_bf16<<<1024, 256>>>(dec3_Wih, rwh + OFF_D3I, rwl + OFF_D3I, (long)GDV * 2 * H2V);
    split_bf16<<<1024, 256>>>(dec1_Whh, rwh + OFF_D1H, rwl + OFF_D1H, (long)GDV * H2V);
    split_bf16<<<1024, 256>>>(dec2_Whh, rwh + OFF_D2H, rwl + OFF_D2H, (long)GDV * H2V);
    split_bf16<<<1024, 256>>>(dec3_Whh, rwh + OFF_D3H, rwl + OFF_D3H, (long)GDV * H2V);

    // ---- encoder layer 0 ----
    cudaMemsetAsync(ehbh, 0, sizeof(__nv_bfloat16) * 2 * 2 * BHV);
    cudaMemsetAsync(ehbl, 0, sizeof(__nv_bfloat16) * 2 * 2 * BHV);
    cudaMemsetAsync(ec,   0, sizeof(float) * 2 * BHV);
    split_bf16<<<1024, 256>>>(x, ah, al, (long)BSV * DD);
    split_bf16<<<1024, 256>>>(enc0_Wih, wh, wl, 2L * GEV * DD);
    gemm_mma<<<dim3(GEV / 128, BSV / 128), 256, G_DSM>>>(ah, al, wh, wl, enc0_b, xg, GEV, DD);
    gemm_mma<<<dim3(GEV / 128, BSV / 128), 256, G_DSM>>>(ah, al, wh + (size_t)GEV * DD, wl + (size_t)GEV * DD,
                                                         enc0_b + GEV, xg + dirXG, GEV, DD);
    const size_t eps = (size_t)2 * BHV;
    for (int t = 0; t < SS; t++) {
        int par = t & 1;
        enc_step_mma<<<dim3(64, 2), 256, E3_DSM>>>(
            ehbh + par * eps, ehbl + par * eps,
            rwh + OFF_E0, rwl + OFF_E0,
            xg, ec,
            ehbh + (par ^ 1) * eps, ehbl + (par ^ 1) * eps,
            h0, t);
    }

    // ---- encoder layer 1 ----
    cudaMemsetAsync(ehbh, 0, sizeof(__nv_bfloat16) * 2 * 2 * BHV);
    cudaMemsetAsync(ehbl, 0, sizeof(__nv_bfloat16) * 2 * 2 * BHV);
    cudaMemsetAsync(ec,   0, sizeof(float) * 2 * BHV);
    split_bf16<<<1024, 256>>>(h0, ah, al, (long)BSV * H2V);
    split_bf16<<<1024, 256>>>(enc1_Wih, wh, wl, 2L * GEV * H2V);
    gemm_mma<<<dim3(GEV / 128, BSV / 128), 256, G_DSM>>>(ah, al, wh, wl, enc1_b, xg, GEV, H2V);
    gemm_mma<<<dim3(GEV / 128, BSV / 128), 256, G_DSM>>>(ah, al, wh + (size_t)GEV * H2V, wl + (size_t)GEV * H2V,
                                                         enc1_b + GEV, xg + dirXG, GEV, H2V);
    for (int t = 0; t < SS; t++) {
        int par = t & 1;
        enc_step_mma<<<dim3(64, 2), 256, E3_DSM>>>(
            ehbh + par * eps, ehbl + par * eps,
            rwh + OFF_E1, rwl + OFF_E1,
            xg, ec,
            ehbh + (par ^ 1) * eps, ehbl + (par ^ 1) * eps,
            enc, t);
    }

    // ---- attn WT (transposed, split) ----
    __nv_bfloat16* wth = wh;
    __nv_bfloat16* wtl = wl;
    for (int i = 0; i < 3; i++)
        transpose_split<<<dim3(32, 32), 256>>>(attnW[i],
                                               wth + (size_t)i * H2V * H2V,
                                               wtl + (size_t)i * H2V * H2V);

    // ---- decoder init ----
    cudaMemsetAsync(dh,   0, sizeof(float) * 6 * BH2);
    cudaMemsetAsync(dcst, 0, sizeof(float) * 3 * BH2);
    cudaMemsetAsync(dhbh, 0, sizeof(__nv_bfloat16) * 6 * BH2);
    cudaMemsetAsync(dhbl, 0, sizeof(__nv_bfloat16) * 6 * BH2);
    set_prev<<<32, 256>>>(x, pvh, pvl);

    // ---- decoder loop ----
    const size_t cs = (size_t)2 * BH2;
    for (int t = 0; t < TT; t++) {
        int par = t & 1;

        // q = h @ WT per head; y-blocks (blockIdx.y==3) emit y_{t-1} + prev feedback
        qgemm_mma<<<dim3(8, 4), 256, G_DSM>>>(
            dhbh + (size_t)par * BH2, dhbl + (size_t)par * BH2, wth, wtl, q,
            dh + 2 * cs + (size_t)par * BH2,   // h3 from step t-1 (same parity)
            out_W, out_b, out, pvh, pvl,
            t - 1, t > 0 ? 1 : 0);

        attend2<<<BB, 256>>>(dh + (size_t)par * BH2, q, attnb[0], attnb[1], attnb[2],
                             enc, cxh, cxl);

        dec_pre<<<dim3(128, 3), 256, RC_DSM>>>(
            cxh, cxl, pvh, pvl,
            dhbh + (size_t)par * BH2, dhbl + (size_t)par * BH2,
            rwh, rwl, dec1_b, dec2_b, dec3_b,
            dcst + 0 * BH2,
            dh + 0 * cs + (size_t)(par ^ 1) * BH2,
            dhbh + 0 * cs + (size_t)(par ^ 1) * BH2, dhbl + 0 * cs + (size_t)(par ^ 1) * BH2,
            gates);

        dec_fin<<<128, 256, RC_DSM>>>(
            dhbh + 0 * cs + (size_t)(par ^ 1) * BH2, dhbl + 0 * cs + (size_t)(par ^ 1) * BH2,
            rwh + OFF_D2I + H2V, rwl + OFF_D2I + H2V, 2 * H2V,
            gates,
            dcst + 1 * BH2,
            dh + 1 * cs + (size_t)(par ^ 1) * BH2,
            dhbh + 1 * cs + (size_t)(par ^ 1) * BH2, dhbl + 1 * cs + (size_t)(par ^ 1) * BH2);

        dec_fin<<<128, 256, RC_DSM>>>(
            dhbh + 1 * cs + (size_t)(par ^ 1) * BH2, dhbl + 1 * cs + (size_t)(par ^ 1) * BH2,
            rwh + OFF_D3I + H2V, rwl + OFF_D3I + H2V, 2 * H2V,
            gates + (size_t)BB * GDV,
            dcst + 2 * BH2,
            dh + 2 * cs + (size_t)(par ^ 1) * BH2,
            dhbh + 2 * cs + (size_t)(par ^ 1) * BH2, dhbl + 2 * cs + (size_t)(par ^ 1) * BH2);
    }

    // final step's projection (h3 of t=59 at parity (59&1)^1 = 0)
    out_proj<<<BB, 64>>>(dh + 2 * cs + (size_t)(((TT - 1) & 1) ^ 1) * BH2,
                         out_W, out_b, out, pvh, pvl, TT - 1);
}

// round 16
// speedup vs baseline: 1.1182x; 1.1182x over previous
#include <cuda_runtime.h>
#include <cuda_bf16.h>
#include <cstdint>
#include <cstddef>

// Problem dims
#define BB  128
#define SS  256
#define DD  64
#define HH  512
#define H2V 1024
#define GEV 2048
#define GDV 4096
#define TT  60
#define BSV (BB*SS)      // 32768
#define BHV (BB*HH)      // 65536
#define BH2 (BB*H2V)     // 131072

// ---------------- scratch (device globals; no allocation allowed) -------------
__device__ float g_xg  [2*BSV*GEV];   // gate preactivations [dir][b][s][g]
__device__ float g_h0  [BSV*H2V];     // encoder layer0 output
__device__ float g_enc [BSV*H2V];     // encoder layer1 output
__device__ float g_ec  [2*BHV];       // enc c [dir][b][h]
__device__ float g_dh  [6*BH2];       // dec h fp32 ping-pong [cell][parity][b][h2]
__device__ float g_dc  [3*BH2];       // dec c
__device__ float g_gates[2*BB*GDV];   // partial gates for cells 2,3
__device__ float g_q   [3*BH2];       // attention queries q = W^T h [head][b][1024]

// bf16 split buffers (wbf reused: enc Wih splits early, then WT splits)
__device__ __nv_bfloat16 g_abf_hi[BSV*H2V];
__device__ __nv_bfloat16 g_abf_lo[BSV*H2V];
__device__ __nv_bfloat16 g_wbf_hi[2*GEV*H2V];
__device__ __nv_bfloat16 g_wbf_lo[2*GEV*H2V];

// recurrent weights pre-split (hi/lo)
#define OFF_E0   0ull
#define OFF_E1   2097152ull
#define OFF_D1I  4194304ull
#define OFF_D2I  8650752ull
#define OFF_D3I  17039360ull
#define OFF_D1H  25427968ull
#define OFF_D2H  29622272ull
#define OFF_D3H  33816576ull
#define RW_TOT   38010880ull
__device__ __nv_bfloat16 g_rwh[RW_TOT];
__device__ __nv_bfloat16 g_rwl[RW_TOT];

// recurrent activations bf16 hi/lo
__device__ __nv_bfloat16 g_ehbh[2*2*BHV];   // enc h [par][dir][b][512]
__device__ __nv_bfloat16 g_ehbl[2*2*BHV];
__device__ __nv_bfloat16 g_dhbh[3*2*BH2];   // dec h [cell][par][b][1024]
__device__ __nv_bfloat16 g_dhbl[3*2*BH2];
__device__ __nv_bfloat16 g_cxh [3*BH2];     // ctx [head][b][1024]
__device__ __nv_bfloat16 g_cxl [3*BH2];
__device__ __nv_bfloat16 g_pvh [BB*DD];     // prev y bf16
__device__ __nv_bfloat16 g_pvl [BB*DD];

__device__ __forceinline__ float sigf(float x) { return 1.0f / (1.0f + expf(-x)); }

__device__ __forceinline__ uint32_t smem_u32(const void* p) {
    uint32_t a;
    asm("{ .reg .u64 t; cvta.to.shared.u64 t, %1; cvt.u32.u64 %0, t; }" : "=r"(a) : "l"(p));
    return a;
}

#define MMA4(d, a, b0v, b1v) \
    asm volatile( \
        "mma.sync.aligned.m16n8k16.row.col.f32.bf16.bf16.f32 " \
        "{%0,%1,%2,%3},{%4,%5,%6,%7},{%8,%9},{%0,%1,%2,%3};" \
        : "+f"((d)[0]), "+f"((d)[1]), "+f"((d)[2]), "+f"((d)[3]) \
        : "r"((a)[0]), "r"((a)[1]), "r"((a)[2]), "r"((a)[3]), "r"(b0v), "r"(b1v))

#define LDSM4(r, addr) \
    asm volatile("ldmatrix.sync.aligned.m8n8.x4.shared.b16 {%0,%1,%2,%3},[%4];" \
        : "=r"((r)[0]), "=r"((r)[1]), "=r"((r)[2]), "=r"((r)[3]) : "r"(addr))

#define LDSM4B(r0, r1, r2, r3, addr) \
    asm volatile("ldmatrix.sync.aligned.m8n8.x4.shared.b16 {%0,%1,%2,%3},[%4];" \
        : "=r"(r0), "=r"(r1), "=r"(r2), "=r"(r3) : "r"(addr))

// =====================  batch HMMA bf16-split GEMM (verified R5) =============
#define G_TILE_B 10240
#define G_STG    (4 * G_TILE_B)
#define G_DSM    (2 * G_STG + 128)

__device__ __forceinline__ void gemm_body(
    const __nv_bfloat16* __restrict__ Ahi, const __nv_bfloat16* __restrict__ Alo,
    const __nv_bfloat16* __restrict__ Whi, const __nv_bfloat16* __restrict__ Wlo,
    const float* __restrict__ bias, float* __restrict__ C, int N, int K,
    int bm, int bn, char* dsm)
{
    const int tid = threadIdx.x, lane = tid & 31, wid = tid >> 5;
    const int wr = wid >> 1, wc = wid & 1;
    const uint32_t sbase = (smem_u32(dsm) + 127u) & ~127u;
    const int nch = K >> 5;

    float acc[2][8][4];
#pragma unroll
    for (int mi = 0; mi < 2; mi++)
#pragma unroll
        for (int ni = 0; ni < 8; ni++)
#pragma unroll
            for (int q = 0; q < 4; q++) acc[mi][ni][q] = 0.0f;

    auto load = [&](int c, int st) {
#pragma unroll
        for (int q = 0; q < 8; q++) {
            int id = q * 256 + tid;
            int t  = id >> 9;
            int r  = (id >> 2) & 127;
            int sg = id & 3;
            const __nv_bfloat16* basep = (t == 0 ? Ahi : t == 1 ? Alo : t == 2 ? Whi : Wlo);
            int grow = (t < 2 ? bm : bn) + r;
            const __nv_bfloat16* src = basep + (size_t)grow * K + c * 32 + sg * 8;
            uint32_t dst = sbase + st * G_STG + t * G_TILE_B + r * 80 + sg * 16;
            asm volatile("cp.async.cg.shared.global [%0], [%1], 16;" :: "r"(dst), "l"(src));
        }
        asm volatile("cp.async.commit_group;" ::: "memory");
    };

    load(0, 0);

    for (int c = 0; c < nch; c++) {
        if (c + 1 < nch) {
            load(c + 1, (c + 1) & 1);
            asm volatile("cp.async.wait_group 1;" ::: "memory");
        } else {
            asm volatile("cp.async.wait_group 0;" ::: "memory");
        }
        __syncthreads();

        const uint32_t stb = sbase + (c & 1) * G_STG;
        const uint32_t aB[2] = { stb, stb + G_TILE_B };
        const uint32_t wB[2] = { stb + 2 * G_TILE_B, stb + 3 * G_TILE_B };
        const int arow = wr * 32 + (lane & 15);
        const int wrow = wc * 64 + (lane & 15);
        const int cc   = (lane >> 4) * 16;

#pragma unroll
        for (int ks = 0; ks < 2; ks++) {
            uint32_t afr[2][2][4];
#pragma unroll
            for (int s = 0; s < 2; s++)
#pragma unroll
                for (int mi = 0; mi < 2; mi++) {
                    uint32_t ad = aB[s] + (uint32_t)(arow + mi * 16) * 80 + ks * 32 + cc;
                    LDSM4(afr[s][mi], ad);
                }
#pragma unroll
            for (int wsp = 0; wsp < 2; wsp++) {
#pragma unroll
                for (int nb = 0; nb < 4; nb++) {
                    uint32_t r0, r1, r2, r3;
                    uint32_t bd = wB[wsp] + (uint32_t)(wrow + nb * 16) * 80 + ks * 32 + cc;
                    LDSM4B(r0, r1, r2, r3, bd);
#pragma unroll
                    for (int mi = 0; mi < 2; mi++) {
                        MMA4(acc[mi][nb * 2],     afr[0][mi], r0, r2);
                        MMA4(acc[mi][nb * 2 + 1], afr[0][mi], r1, r3);
                        if (wsp == 0) {
                            MMA4(acc[mi][nb * 2],     afr[1][mi], r0, r2);
                            MMA4(acc[mi][nb * 2 + 1], afr[1][mi], r1, r3);
                        }
                    }
                }
            }
        }
        __syncthreads();
    }

#pragma unroll
    for (int mi = 0; mi < 2; mi++) {
#pragma unroll
        for (int ni = 0; ni < 8; ni++) {
            int r0 = bm + wr * 32 + mi * 16 + (lane >> 2);
            int c0 = bn + wc * 64 + ni * 8 + (lane & 3) * 2;
            float b0v = bias ? bias[c0] : 0.0f;
            float b1v = bias ? bias[c0 + 1] : 0.0f;
            float2 v0 = { acc[mi][ni][0] + b0v, acc[mi][ni][1] + b1v };
            float2 v1 = { acc[mi][ni][2] + b0v, acc[mi][ni][3] + b1v };
            *(float2*)&C[(size_t)r0 * N + c0]       = v0;
            *(float2*)&C[(size_t)(r0 + 8) * N + c0] = v1;
        }
    }
}

__global__ __launch_bounds__(256) void gemm_mma(
    const __nv_bfloat16* __restrict__ Ahi, const __nv_bfloat16* __restrict__ Alo,
    const __nv_bfloat16* __restrict__ Whi, const __nv_bfloat16* __restrict__ Wlo,
    const float* __restrict__ bias, float* __restrict__ C, int N, int K)
{
    extern __shared__ char dsm[];
    gemm_body(Ahi, Alo, Whi, Wlo, bias, C, N, K, blockIdx.y * 128, blockIdx.x * 128, dsm);
}

// q[head] = h[head] @ WT[head]
__global__ __launch_bounds__(256) void qgemm_mma(
    const __nv_bfloat16* __restrict__ hbh, const __nv_bfloat16* __restrict__ hbl,
    const __nv_bfloat16* __restrict__ wth, const __nv_bfloat16* __restrict__ wtl,
    float* __restrict__ q)
{
    extern __shared__ char dsm[];
    const int head = blockIdx.y;
    const size_t cs = (size_t)2 * BH2;
    gemm_body(hbh + (size_t)head * cs, hbl + (size_t)head * cs,
              wth + (size_t)head * H2V * H2V, wtl + (size_t)head * H2V * H2V,
              nullptr, q + (size_t)head * BH2, H2V, H2V,
              0, blockIdx.x * 128, dsm);
}

// fp32 -> bf16 hi/lo split
__global__ void split_bf16(const float* __restrict__ s, __nv_bfloat16* __restrict__ hi,
                           __nv_bfloat16* __restrict__ lo, long n)
{
    long stride = (long)gridDim.x * blockDim.x;
    for (long i = blockIdx.x * (long)blockDim.x + threadIdx.x; i < n; i += stride) {
        float v = s[i];
        __nv_bfloat16 h = __float2bfloat16(v);
        hi[i] = h;
        lo[i] = __float2bfloat16(v - __bfloat162float(h));
    }
}

// transpose + split: WT[e][d] = W[d][e], 1024x1024, bf16 hi/lo
__global__ __launch_bounds__(256) void transpose_split(
    const float* __restrict__ W, __nv_bfloat16* __restrict__ hi, __nv_bfloat16* __restrict__ lo)
{
    __shared__ float tile[32][33];
    const int bx = blockIdx.x * 32, by = blockIdx.y * 32;
    const int tx = threadIdx.x & 31, ty = threadIdx.x >> 5;
#pragma unroll
    for (int i = 0; i < 32; i += 8)
        tile[ty + i][tx] = W[(size_t)(bx + ty + i) * H2V + by + tx];
    __syncthreads();
#pragma unroll
    for (int i = 0; i < 32; i += 8) {
        float v = tile[tx][ty + i];
        size_t idx = (size_t)(by + ty + i) * H2V + bx + tx;
        __nv_bfloat16 h = __float2bfloat16(v);
        hi[idx] = h;
        lo[idx] = __float2bfloat16(v - __bfloat162float(h));
    }
}

// =====================  HMMA recurrent cell machinery ========================
// Block tile M=128 (batch) x N=32 (4 gates x 8 units); 8 warps of 16x32.
// K chunks of 64. 144B rows (conflict-free ldmatrix).
#define RC_ATILE 18432                 // 128*144
#define RC_WOFF  36864                 // 2*RC_ATILE
#define RC_WTILE 4608                  // 32*144
#define RC_STG   46080
// dec_pre: 2-stage (2 CTAs/SM at 109.5KB; grid 384 needs the occupancy)
#define RC_GS_OFF (2 * RC_STG)         // 92160
#define RC_DSM   (RC_GS_OFF + 128 * 34 * 4)   // 109568
// 3-stage (encoder + dec_fin: single-wave grids, latency-bound)
#define E3_GS_OFF (3 * RC_STG)         // 138240
#define E3_DSM   (E3_GS_OFF + 128 * 34 * 4)   // 155648

struct Seg {
    const __nv_bfloat16 *Ah, *Al, *Wh, *Wl;
    int lda, ldw, nch;   // nch in 64-wide chunks
};

__device__ __forceinline__ void rc_load64(const Seg& s, int kc, uint32_t stb,
                                          int tid, int ubase, int GST)
{
#pragma unroll
    for (int q = 0; q < 10; q++) {
        int id = q * 256 + tid;      // 0..2559
        uint32_t dst; const __nv_bfloat16* src;
        if (id < 2048) {             // A: 2 tiles x 128 rows x 8 segs
            int t = id >> 10, r = (id >> 3) & 127, sg = id & 7;
            src = (t ? s.Al : s.Ah) + (size_t)r * s.lda + kc + sg * 8;
            dst = stb + t * RC_ATILE + r * 144 + sg * 16;
        } else {                     // W: 2 tiles x 32 rows x 8 segs
            int id2 = id - 2048;     // 0..511
            int t = id2 >> 8, r = (id2 >> 3) & 31, sg = id2 & 7;
            int grow = (r >> 3) * GST + ubase + (r & 7);
            src = (t ? s.Wl : s.Wh) + (size_t)grow * s.ldw + kc + sg * 8;
            dst = stb + RC_WOFF + t * RC_WTILE + r * 144 + sg * 16;
        }
        asm volatile("cp.async.cg.shared.global [%0], [%1], 16;" :: "r"(dst), "l"(src));
    }
    asm volatile("cp.async.commit_group;" ::: "memory");
}

__device__ __forceinline__ void rc_consume64(uint32_t stb, int wid, int lane,
                                             float (*acc)[4])
{
    const uint32_t cc   = (lane >> 4) * 16;
    const uint32_t arow = wid * 16 + (lane & 15);
    const uint32_t wrow = (lane & 15);
#pragma unroll
    for (int ks = 0; ks < 4; ks++) {
        uint32_t ah[4], al[4];
        LDSM4(ah, stb + arow * 144 + ks * 32 + cc);
        LDSM4(al, stb + RC_ATILE + arow * 144 + ks * 32 + cc);
        uint32_t b0,b1,b2,b3,b4,b5,b6,b7;
        LDSM4B(b0,b1,b2,b3, stb + RC_WOFF + wrow * 144 + ks * 32 + cc);
        LDSM4B(b4,b5,b6,b7, stb + RC_WOFF + (wrow + 16) * 144 + ks * 32 + cc);
        uint32_t l0,l1,l2,l3,l4,l5,l6,l7;
        LDSM4B(l0,l1,l2,l3, stb + RC_WOFF + RC_WTILE + wrow * 144 + ks * 32 + cc);
        LDSM4B(l4,l5,l6,l7, stb + RC_WOFF + RC_WTILE + (wrow + 16) * 144 + ks * 32 + cc);
        MMA4(acc[0], ah, b0, b2); MMA4(acc[0], al, b0, b2); MMA4(acc[0], ah, l0, l2);
        MMA4(acc[1], ah, b1, b3); MMA4(acc[1], al, b1, b3); MMA4(acc[1], ah, l1, l3);
        MMA4(acc[2], ah, b4, b6); MMA4(acc[2], al, b4, b6); MMA4(acc[2], ah, l4, l6);
        MMA4(acc[3], ah, b5, b7); MMA4(acc[3], al, b5, b7); MMA4(acc[3], ah, l5, l7);
    }
}

__device__ __forceinline__ void rc_epilogue_to_smem(float (*gs)[34], float (*acc)[4],
                                                    int wid, int lane)
{
#pragma unroll
    for (int nt = 0; nt < 4; nt++) {
        int r0 = wid * 16 + (lane >> 2);
        int c0 = nt * 8 + (lane & 3) * 2;
        gs[r0][c0]     = acc[nt][0];
        gs[r0][c0 + 1] = acc[nt][1];
        gs[r0 + 8][c0]     = acc[nt][2];
        gs[r0 + 8][c0 + 1] = acc[nt][3];
    }
}

// 2-stage pipeline driver over a segment list (dec_pre)
__device__ __forceinline__ void rc_run(const Seg* segs, int total, uint32_t sb,
                                       int tid, int wid, int lane, int ubase, int GST,
                                       float (*acc)[4])
{
    int si = 0, kc = 0;
    rc_load64(segs[0], 0, sb, tid, ubase, GST);
    for (int ci = 0; ci < total; ci++) {
        int nsi = si, nkc = kc + 64;
        if (nkc >= segs[nsi].nch * 64) { nsi++; nkc = 0; }
        if (ci + 1 < total) {
            rc_load64(segs[nsi], nkc, sb + ((ci + 1) & 1) * RC_STG, tid, ubase, GST);
            asm volatile("cp.async.wait_group 1;" ::: "memory");
        } else {
            asm volatile("cp.async.wait_group 0;" ::: "memory");
        }
        __syncthreads();
        rc_consume64(sb + (ci & 1) * RC_STG, wid, lane, acc);
        __syncthreads();
        si = nsi; kc = nkc;
    }
}

// 3-stage single-segment driver (encoder step, dec_fin)
__device__ __forceinline__ void rc_run3(const Seg& s, int total, uint32_t sb,
                                        int tid, int wid, int lane, int ubase, int GST,
                                        float (*acc)[4])
{
    rc_load64(s, 0, sb, tid, ubase, GST);
    if (total > 1) rc_load64(s, 64, sb + RC_STG, tid, ubase, GST);
    for (int ci = 0; ci < total; ci++) {
        if (ci + 2 < total)
            rc_load64(s, (ci + 2) * 64, sb + ((ci + 2) % 3) * RC_STG, tid, ubase, GST);
        int inflight = total - 1 - ci; if (inflight > 2) inflight = 2;
        if (inflight >= 2)      asm volatile("cp.async.wait_group 2;" ::: "memory");
        else if (inflight == 1) asm volatile("cp.async.wait_group 1;" ::: "memory");
        else                    asm volatile("cp.async.wait_group 0;" ::: "memory");
        __syncthreads();
        rc_consume64(sb + (ci % 3) * RC_STG, wid, lane, acc);
        __syncthreads();
    }
}

// ---------------- encoder recurrent step (HMMA, 3-stage pipeline) -------------
__global__ __launch_bounds__(256) void enc_step_mma(
    const __nv_bfloat16* __restrict__ hh, const __nv_bfloat16* __restrict__ hl,
    const __nv_bfloat16* __restrict__ Wh, const __nv_bfloat16* __restrict__ Wl,
    const float* __restrict__ xg, float* __restrict__ cst,
    __nv_bfloat16* __restrict__ hho, __nv_bfloat16* __restrict__ hlo,
    float* __restrict__ hs, int t)
{
    extern __shared__ char dsm[];
    const int tid = threadIdx.x, lane = tid & 31, wid = tid >> 5;
    const int dir = blockIdx.y, ubase = blockIdx.x * 8;
    const int td = dir ? (SS - 1 - t) : t;
    const uint32_t sb = smem_u32(dsm);
    float (*gs)[34] = (float (*)[34])(dsm + E3_GS_OFF);

    Seg s = { hh + (size_t)dir * BHV, hl + (size_t)dir * BHV,
              Wh + (size_t)dir * GEV * HH, Wl + (size_t)dir * GEV * HH,
              HH, HH, 8 };

    float acc[4][4];
#pragma unroll
    for (int nt = 0; nt < 4; nt++)
#pragma unroll
        for (int q = 0; q < 4; q++) acc[nt][q] = 0.0f;

    rc_run3(s, 8, sb, tid, wid, lane, ubase, HH, acc);

    rc_epilogue_to_smem(gs, acc, wid, lane);
    __syncthreads();

    const float* xgp = xg + (size_t)dir * BSV * GEV;
    float* cp = cst + (size_t)dir * BHV;
#pragma unroll
    for (int k = 0; k < 4; k++) {
        int idx = k * 256 + tid;
        int b = idx >> 3, u = idx & 7;
        int uu = ubase + u;
        size_t xrow = ((size_t)b * SS + td) * GEV;
        float gi = gs[b][u]      + xgp[xrow + uu];
        float gf = gs[b][8 + u]  + xgp[xrow + 512 + uu];
        float gg = gs[b][16 + u] + xgp[xrow + 1024 + uu];
        float go = gs[b][24 + u] + xgp[xrow + 1536 + uu];
        int hidx = b * HH + uu;
        float c = sigf(gf) * cp[hidx] + sigf(gi) * tanhf(gg);
        float h = sigf(go) * tanhf(c);
        cp[hidx] = c;
        hs[((size_t)b * SS + td) * H2V + dir * HH + uu] = h;
        __nv_bfloat16 hb = __float2bfloat16(h);
        hho[(size_t)dir * BHV + hidx] = hb;
        hlo[(size_t)dir * BHV + hidx] = __float2bfloat16(h - __bfloat162float(hb));
    }
}

// ---------------- decoder: parallel pre-pass (cell1 full + cells 2,3 partial) -
__global__ __launch_bounds__(256) void dec_pre(
    const __nv_bfloat16* __restrict__ cxh, const __nv_bfloat16* __restrict__ cxl,
    const __nv_bfloat16* __restrict__ pvh, const __nv_bfloat16* __restrict__ pvl,
    const __nv_bfloat16* __restrict__ hph, const __nv_bfloat16* __restrict__ hpl,
    const __nv_bfloat16* __restrict__ rwh, const __nv_bfloat16* __restrict__ rwl,
    const float* __restrict__ b1, const float* __restrict__ b2, const float* __restrict__ b3,
    float* __restrict__ cst1, float* __restrict__ h1fo,
    __nv_bfloat16* __restrict__ h1ho, __nv_bfloat16* __restrict__ h1lo,
    float* __restrict__ gates)
{
    extern __shared__ char dsm[];
    const int tid = threadIdx.x, lane = tid & 31, wid = tid >> 5;
    const int ubase = blockIdx.x * 8;
    const int c = blockIdx.y;
    const uint32_t sb = smem_u32(dsm);
    float (*gs)[34] = (float (*)[34])(dsm + RC_GS_OFF);
    const size_t cs = (size_t)2 * BH2;

    const unsigned long long offI = c == 0 ? OFF_D1I : (c == 1 ? OFF_D2I : OFF_D3I);
    const unsigned long long offH = c == 0 ? OFF_D1H : (c == 1 ? OFF_D2H : OFF_D3H);
    const int ldih = c == 0 ? (H2V + DD) : (2 * H2V);
    const float* bias = c == 0 ? b1 : (c == 1 ? b2 : b3);

    Seg segs[3];
    int total;
    segs[0] = { cxh + (size_t)c * BH2, cxl + (size_t)c * BH2,
                rwh + offI, rwl + offI, H2V, ldih, 16 };
    if (c == 0) {
        segs[1] = { pvh, pvl, rwh + offI + H2V, rwl + offI + H2V, DD, ldih, 1 };
        segs[2] = { hph, hpl, rwh + offH, rwl + offH, H2V, H2V, 16 };
        total = 33;
    } else {
        segs[1] = { hph + (size_t)c * cs, hpl + (size_t)c * cs,
                    rwh + offH, rwl + offH, H2V, H2V, 16 };
        total = 32;
    }

    float acc[4][4];
#pragma unroll
    for (int nt = 0; nt < 4; nt++)
#pragma unroll
        for (int q = 0; q < 4; q++) acc[nt][q] = 0.0f;

    rc_run(segs, total, sb, tid, wid, lane, ubase, H2V, acc);

    rc_epilogue_to_smem(gs, acc, wid, lane);
    __syncthreads();

    if (c == 0) {
#pragma unroll
        for (int k = 0; k < 4; k++) {
            int idx = k * 256 + tid;
            int b = idx >> 3, u = idx & 7;
            int uu = ubase + u;
            float gi = gs[b][u]      + bias[uu];
            float gf = gs[b][8 + u]  + bias[1024 + uu];
            float gg = gs[b][16 + u] + bias[2048 + uu];
            float go = gs[b][24 + u] + bias[3072 + uu];
            int hidx = b * H2V + uu;
            float cc = sigf(gf) * cst1[hidx] + sigf(gi) * tanhf(gg);
            float h = sigf(go) * tanhf(cc);
            cst1[hidx] = cc;
            h1fo[hidx] = h;
            __nv_bfloat16 hb = __float2bfloat16(h);
            h1ho[hidx] = hb;
            h1lo[hidx] = __float2bfloat16(h - __bfloat162float(hb));
        }
    } else {
        float* gp = gates + (size_t)(c - 1) * BB * GDV;
#pragma unroll
        for (int k = 0; k < 4; k++) {
            int idx = k * 256 + tid;
            int b = idx >> 3, u = idx & 7;
            int uu = ubase + u;
            gp[(size_t)b * GDV + uu]        = gs[b][u]      + bias[uu];
            gp[(size_t)b * GDV + 1024 + uu] = gs[b][8 + u]  + bias[1024 + uu];
            gp[(size_t)b * GDV + 2048 + uu] = gs[b][16 + u] + bias[2048 + uu];
            gp[(size_t)b * GDV + 3072 + uu] = gs[b][24 + u] + bias[3072 + uu];
        }
    }
}

// ---------------- decoder: finish cell (3-stage; single wave grid=128) --------
__global__ __launch_bounds__(256) void dec_fin(
    const __nv_bfloat16* __restrict__ ih, const __nv_bfloat16* __restrict__ il,
    const __nv_bfloat16* __restrict__ Wh, const __nv_bfloat16* __restrict__ Wl,
    int ldw,
    const float* __restrict__ gpart,
    float* __restrict__ cst, float* __restrict__ hfo,
    __nv_bfloat16* __restrict__ hho, __nv_bfloat16* __restrict__ hlo)
{
    extern __shared__ char dsm[];
    const int tid = threadIdx.x, lane = tid & 31, wid = tid >> 5;
    const int ubase = blockIdx.x * 8;
    const uint32_t sb = smem_u32(dsm);
    float (*gs)[34] = (float (*)[34])(dsm + E3_GS_OFF);

    Seg s = { ih, il, Wh, Wl, H2V, ldw, 16 };

    float acc[4][4];
#pragma unroll
    for (int nt = 0; nt < 4; nt++)
#pragma unroll
        for (int q = 0; q < 4; q++) acc[nt][q] = 0.0f;

    rc_run3(s, 16, sb, tid, wid, lane, ubase, H2V, acc);

    rc_epilogue_to_smem(gs, acc, wid, lane);
    __syncthreads();

#pragma unroll
    for (int k = 0; k < 4; k++) {
        int idx = k * 256 + tid;
        int b = idx >> 3, u = idx & 7;
        int uu = ubase + u;
        const float* gp = gpart + (size_t)b * GDV;
        float gi = gs[b][u]      + gp[uu];
        float gf = gs[b][8 + u]  + gp[1024 + uu];
        float gg = gs[b][16 + u] + gp[2048 + uu];
        float go = gs[b][24 + u] + gp[3072 + uu];
        int hidx = b * H2V + uu;
        float cc = sigf(gf) * cst[hidx] + sigf(gi) * tanhf(gg);
        float h = sigf(go) * tanhf(cc);
        cst[hidx] = cc;
        hfo[hidx] = h;
        __nv_bfloat16 hb = __float2bfloat16(h);
        hho[hidx] = hb;
        hlo[hidx] = __float2bfloat16(h - __bfloat162float(hb));
    }
}

// ---------------- q-based fused 3-head attention ------------------------------
__global__ __launch_bounds__(256) void attend2(
    const float* __restrict__ dh,
    const float* __restrict__ q,
    const float* __restrict__ ab0, const float* __restrict__ ab1, const float* __restrict__ ab2,
    const float* __restrict__ enc,
    __nv_bfloat16* __restrict__ cxh, __nv_bfloat16* __restrict__ cxl)
{
    const int b = blockIdx.x, tid = threadIdx.x, lane = tid & 31, wid = tid >> 5;
    __shared__ float sa[3][SS];
    __shared__ float red[3][8];
    __shared__ float shb[3];
    __shared__ float redm[3][8];
    __shared__ float reds[3][8];

    // fused hb phase: all 3 heads in one pass, one barrier set
    {
        float p0 = 0.0f, p1 = 0.0f, p2 = 0.0f;
        const float* h0p = dh + (size_t)0 * 2 * BH2 + (size_t)b * H2V;
        const float* h1p = dh + (size_t)1 * 2 * BH2 + (size_t)b * H2V;
        const float* h2p = dh + (size_t)2 * 2 * BH2 + (size_t)b * H2V;
        for (int d = tid; d < H2V; d += 256) {
            p0 += h0p[d] * ab0[d];
            p1 += h1p[d] * ab1[d];
            p2 += h2p[d] * ab2[d];
        }
#pragma unroll
        for (int off = 16; off; off >>= 1) {
            p0 += __shfl_xor_sync(0xffffffffu, p0, off);
            p1 += __shfl_xor_sync(0xffffffffu, p1, off);
            p2 += __shfl_xor_sync(0xffffffffu, p2, off);
        }
        if (lane == 0) { red[0][wid] = p0; red[1][wid] = p1; red[2][wid] = p2; }
        __syncthreads();
        if (tid < 3) {
            float s = 0.0f;
#pragma unroll
            for (int i = 0; i < 8; i++) s += red[tid][i];
            shb[tid] = s;
        }
        __syncthreads();
    }

    float4 qr[3][8];
#pragma unroll
    for (int hd = 0; hd < 3; hd++)
#pragma unroll
        for (int k = 0; k < 8; k++)
            qr[hd][k] = *(const float4*)&q[(size_t)hd * BH2 + (size_t)b * H2V + k * 128 + lane * 4];

    const float* eb = enc + (size_t)b * SS * H2V;
    for (int s = wid * 32; s < wid * 32 + 32; s++) {
        const float* er = eb + (size_t)s * H2V + lane * 4;
        float a0 = 0.0f, a1 = 0.0f, a2 = 0.0f;
#pragma unroll
        for (int k = 0; k < 8; k++) {
            float4 ev = *(const float4*)(er + k * 128);
            a0 += ev.x * qr[0][k].x + ev.y * qr[0][k].y + ev.z * qr[0][k].z + ev.w * qr[0][k].w;
            a1 += ev.x * qr[1][k].x + ev.y * qr[1][k].y + ev.z * qr[1][k].z + ev.w * qr[1][k].w;
            a2 += ev.x * qr[2][k].x + ev.y * qr[2][k].y + ev.z * qr[2][k].z + ev.w * qr[2][k].w;
        }
#pragma unroll
        for (int off = 16; off; off >>= 1) {
            a0 += __shfl_xor_sync(0xffffffffu, a0, off);
            a1 += __shfl_xor_sync(0xffffffffu, a1, off);
            a2 += __shfl_xor_sync(0xffffffffu, a2, off);
        }
        if (lane == 0) {
            sa[0][s] = a0 + shb[0];
            sa[1][s] = a1 + shb[1];
            sa[2][s] = a2 + shb[2];
        }
    }
    __syncthreads();

    float ev3[3];
#pragma unroll
    for (int hd = 0; hd < 3; hd++) {
        float m = sa[hd][tid];
#pragma unroll
        for (int off = 16; off; off >>= 1)
            m = fmaxf(m, __shfl_xor_sync(0xffffffffu, m, off));
        if (lane == 0) redm[hd][wid] = m;
    }
    __syncthreads();
#pragma unroll
    for (int hd = 0; hd < 3; hd++) {
        float m = redm[hd][0];
#pragma unroll
        for (int i = 1; i < 8; i++) m = fmaxf(m, redm[hd][i]);
        float e = expf(sa[hd][tid] - m);
        ev3[hd] = e;
        float ssum = e;
#pragma unroll
        for (int off = 16; off; off >>= 1)
            ssum += __shfl_xor_sync(0xffffffffu, ssum, off);
        if (lane == 0) reds[hd][wid] = ssum;
    }
    __syncthreads();
#pragma unroll
    for (int hd = 0; hd < 3; hd++) {
        float tot = reds[hd][0];
#pragma unroll
        for (int i = 1; i < 8; i++) tot += reds[hd][i];
        sa[hd][tid] = ev3[hd] / tot;
    }
    __syncthreads();

    float4 a0 = {0,0,0,0}, a1 = {0,0,0,0}, a2 = {0,0,0,0};
    const float* er = enc + (size_t)b * SS * H2V + tid * 4;
#pragma unroll 4
    for (int s = 0; s < SS; s++) {
        float4 ev4 = *(const float4*)(er + (size_t)s * H2V);
        float w0 = sa[0][s], w1 = sa[1][s], w2 = sa[2][s];
        a0.x += w0 * ev4.x; a0.y += w0 * ev4.y; a0.z += w0 * ev4.z; a0.w += w0 * ev4.w;
        a1.x += w1 * ev4.x; a1.y += w1 * ev4.y; a1.z += w1 * ev4.z; a1.w += w1 * ev4.w;
        a2.x += w2 * ev4.x; a2.y += w2 * ev4.y; a2.z += w2 * ev4.z; a2.w += w2 * ev4.w;
    }
#pragma unroll
    for (int hd = 0; hd < 3; hd++) {
        float4 v = hd == 0 ? a0 : hd == 1 ? a1 : a2;
        size_t base = (size_t)hd * BH2 + (size_t)b * H2V + tid * 4;
        float vv[4] = { v.x, v.y, v.z, v.w };
#pragma unroll
        for (int qd = 0; qd < 4; qd++) {
            __nv_bfloat16 hb = __float2bfloat16(vv[qd]);
            cxh[base + qd] = hb;
            cxl[base + qd] = __float2bfloat16(vv[qd] - __bfloat162float(hb));
        }
    }
}

// ---------------- output projection + feedback --------------------------------
__global__ __launch_bounds__(64) void out_proj(
    const float* __restrict__ h,
    const float* __restrict__ W,
    const float* __restrict__ bias,
    float* __restrict__ y,
    __nv_bfloat16* __restrict__ pvh, __nv_bfloat16* __restrict__ pvl,
    int t)
{
    const int b = blockIdx.x, d = threadIdx.x;
    __shared__ float sh[H2V];
    for (int i = d; i < H2V; i += 64) sh[i] = h[(size_t)b * H2V + i];
    __syncthreads();
    float acc = bias[d];
    const float* wr = W + (size_t)d * H2V;
    for (int k = 0; k < H2V; k += 4) {
        float4 wv = *(const float4*)(wr + k);
        acc += wv.x * sh[k] + wv.y * sh[k + 1] + wv.z * sh[k + 2] + wv.w * sh[k + 3];
    }
    y[((size_t)b * TT + t) * DD + d] = acc;
    __nv_bfloat16 hb = __float2bfloat16(acc);
    pvh[b * DD + d] = hb;
    pvl[b * DD + d] = __float2bfloat16(acc - __bfloat162float(hb));
}

__global__ void set_prev(const float* __restrict__ x,
                         __nv_bfloat16* __restrict__ pvh, __nv_bfloat16* __restrict__ pvl)
{
    int i = blockIdx.x * blockDim.x + threadIdx.x;
    if (i < BB * DD) {
        int b = i / DD, d = i % DD;
        float v = x[((size_t)b * SS + (SS - 1)) * DD + d];
        __nv_bfloat16 hb = __float2bfloat16(v);
        pvh[i] = hb;
        pvl[i] = __float2bfloat16(v - __bfloat162float(hb));
    }
}

// ---------------- host orchestration ------------------------------------------
extern "C" void kernel_launch(void* const* d_in, const int* in_sizes, int n_in,
                              void* d_out, int out_size)
{
    (void)in_sizes; (void)n_in; (void)out_size;
    const float* x        = (const float*)d_in[0];
    const float* enc0_Wih = (const float*)d_in[1];
    const float* enc0_Whh = (const float*)d_in[2];
    const float* enc0_b   = (const float*)d_in[3];
    const float* enc1_Wih = (const float*)d_in[4];
    const float* enc1_Whh = (const float*)d_in[5];
    const float* enc1_b   = (const float*)d_in[6];
    const float* attnW[3] = {(const float*)d_in[7],  (const float*)d_in[9],  (const float*)d_in[11]};
    const float* attnb[3] = {(const float*)d_in[8],  (const float*)d_in[10], (const float*)d_in[12]};
    const float* dec1_Wih = (const float*)d_in[13];
    const float* dec1_Whh = (const float*)d_in[14];
    const float* dec1_b   = (const float*)d_in[15];
    const float* dec2_Wih = (const float*)d_in[16];
    const float* dec2_Whh = (const float*)d_in[17];
    const float* dec2_b   = (const float*)d_in[18];
    const float* dec3_Wih = (const float*)d_in[19];
    const float* dec3_Whh = (const float*)d_in[20];
    const float* dec3_b   = (const float*)d_in[21];
    const float* out_W    = (const float*)d_in[22];
    const float* out_b    = (const float*)d_in[23];
    float* out = (float*)d_out;

    float *xg, *h0, *enc, *ec, *dh, *dcst, *gates, *q;
    __nv_bfloat16 *ah, *al, *wh, *wl, *rwh, *rwl;
    __nv_bfloat16 *ehbh, *ehbl, *dhbh, *dhbl, *cxh, *cxl, *pvh, *pvl;
    cudaGetSymbolAddress((void**)&xg,    g_xg);
    cudaGetSymbolAddress((void**)&h0,    g_h0);
    cudaGetSymbolAddress((void**)&enc,   g_enc);
    cudaGetSymbolAddress((void**)&ec,    g_ec);
    cudaGetSymbolAddress((void**)&dh,    g_dh);
    cudaGetSymbolAddress((void**)&dcst,  g_dc);
    cudaGetSymbolAddress((void**)&gates, g_gates);
    cudaGetSymbolAddress((void**)&q,     g_q);
    cudaGetSymbolAddress((void**)&ah,    g_abf_hi);
    cudaGetSymbolAddress((void**)&al,    g_abf_lo);
    cudaGetSymbolAddress((void**)&wh,    g_wbf_hi);
    cudaGetSymbolAddress((void**)&wl,    g_wbf_lo);
    cudaGetSymbolAddress((void**)&rwh,   g_rwh);
    cudaGetSymbolAddress((void**)&rwl,   g_rwl);
    cudaGetSymbolAddress((void**)&ehbh,  g_ehbh);
    cudaGetSymbolAddress((void**)&ehbl,  g_ehbl);
    cudaGetSymbolAddress((void**)&dhbh,  g_dhbh);
    cudaGetSymbolAddress((void**)&dhbl,  g_dhbl);
    cudaGetSymbolAddress((void**)&cxh,   g_cxh);
    cudaGetSymbolAddress((void**)&cxl,   g_cxl);
    cudaGetSymbolAddress((void**)&pvh,   g_pvh);
    cudaGetSymbolAddress((void**)&pvl,   g_pvl);

    cudaFuncSetAttribute(gemm_mma,     cudaFuncAttributeMaxDynamicSharedMemorySize, G_DSM);
    cudaFuncSetAttribute(qgemm_mma,    cudaFuncAttributeMaxDynamicSharedMemorySize, G_DSM);
    cudaFuncSetAttribute(enc_step_mma, cudaFuncAttributeMaxDynamicSharedMemorySize, E3_DSM);
    cudaFuncSetAttribute(dec_pre,      cudaFuncAttributeMaxDynamicSharedMemorySize, RC_DSM);
    cudaFuncSetAttribute(dec_fin,      cudaFuncAttributeMaxDynamicSharedMemorySize, E3_DSM);

    const size_t dirXG = (size_t)BSV * GEV;

    // ---- pre-split recurrent weights ----
    split_bf16<<<1024, 256>>>(enc0_Whh, rwh + OFF_E0,  rwl + OFF_E0,  2L * GEV * HH);
    split_bf16<<<1024, 256>>>(enc1_Whh, rwh + OFF_E1,  rwl + OFF_E1,  2L * GEV * HH);
    split_bf16<<<1024, 256>>>(dec1_Wih, rwh + OFF_D1I, rwl + OFF_D1I, (long)GDV * (H2V + DD));
    split_bf16<<<1024, 256>>>(dec2_Wih, rwh + OFF_D2I, rwl + OFF_D2I, (long)GDV * 2 * H2V);
    split_bf16<<<1024, 256>>>(dec3_Wih, rwh + OFF_D3I, rwl + OFF_D3I, (long)GDV * 2 * H2V);
    split_bf16<<<1024, 256>>>(dec1_Whh, rwh + OFF_D1H, rwl + OFF_D1H, (long)GDV * H2V);
    split_bf16<<<1024, 256>>>(dec2_Whh, rwh + OFF_D2H, rwl + OFF_D2H, (long)GDV * H2V);
    split_bf16<<<1024, 256>>>(dec3_Whh, rwh + OFF_D3H, rwl + OFF_D3H, (long)GDV * H2V);

    // ---- encoder layer 0 ----
    cudaMemsetAsync(ehbh, 0, sizeof(__nv_bfloat16) * 2 * 2 * BHV);
    cudaMemsetAsync(ehbl, 0, sizeof(__nv_bfloat16) * 2 * 2 * BHV);
    cudaMemsetAsync(ec,   0, sizeof(float) * 2 * BHV);
    split_bf16<<<1024, 256>>>(x, ah, al, (long)BSV * DD);
    split_bf16<<<1024, 256>>>(enc0_Wih, wh, wl, 2L * GEV * DD);
    gemm_mma<<<dim3(GEV / 128, BSV / 128), 256, G_DSM>>>(ah, al, wh, wl, enc0_b, xg, GEV, DD);
    gemm_mma<<<dim3(GEV / 128, BSV / 128), 256, G_DSM>>>(ah, al, wh + (size_t)GEV * DD, wl + (size_t)GEV * DD,
                                                         enc0_b + GEV, xg + dirXG, GEV, DD);
    const size_t eps = (size_t)2 * BHV;
    for (int t = 0; t < SS; t++) {
        int par = t & 1;
        enc_step_mma<<<dim3(64, 2), 256, E3_DSM>>>(
            ehbh + par * eps, ehbl + par * eps,
            rwh + OFF_E0, rwl + OFF_E0,
            xg, ec,
            ehbh + (par ^ 1) * eps, ehbl + (par ^ 1) * eps,
            h0, t);
    }

    // ---- encoder layer 1 ----
    cudaMemsetAsync(ehbh, 0, sizeof(__nv_bfloat16) * 2 * 2 * BHV);
    cudaMemsetAsync(ehbl, 0, sizeof(__nv_bfloat16) * 2 * 2 * BHV);
    cudaMemsetAsync(ec,   0, sizeof(float) * 2 * BHV);
    split_bf16<<<1024, 256>>>(h0, ah, al, (long)BSV * H2V);
    split_bf16<<<1024, 256>>>(enc1_Wih, wh, wl, 2L * GEV * H2V);
    gemm_mma<<<dim3(GEV / 128, BSV / 128), 256, G_DSM>>>(ah, al, wh, wl, enc1_b, xg, GEV, H2V);
    gemm_mma<<<dim3(GEV / 128, BSV / 128), 256, G_DSM>>>(ah, al, wh + (size_t)GEV * H2V, wl + (size_t)GEV * H2V,
                                                         enc1_b + GEV, xg + dirXG, GEV, H2V);
    for (int t = 0; t < SS; t++) {
        int par = t & 1;
        enc_step_mma<<<dim3(64, 2), 256, E3_DSM>>>(
            ehbh + par * eps, ehbl + par * eps,
            rwh + OFF_E1, rwl + OFF_E1,
            xg, ec,
            ehbh + (par ^ 1) * eps, ehbl + (par ^ 1) * eps,
            enc, t);
    }

    // ---- attn WT (transposed, split) ----
    __nv_bfloat16* wth = wh;
    __nv_bfloat16* wtl = wl;
    for (int i = 0; i < 3; i++)
        transpose_split<<<dim3(32, 32), 256>>>(attnW[i],
                                               wth + (size_t)i * H2V * H2V,
                                               wtl + (size_t)i * H2V * H2V);

    // ---- decoder init ----
    cudaMemsetAsync(dh,   0, sizeof(float) * 6 * BH2);
    cudaMemsetAsync(dcst, 0, sizeof(float) * 3 * BH2);
    cudaMemsetAsync(dhbh, 0, sizeof(__nv_bfloat16) * 6 * BH2);
    cudaMemsetAsync(dhbl, 0, sizeof(__nv_bfloat16) * 6 * BH2);
    set_prev<<<32, 256>>>(x, pvh, pvl);

    // ---- decoder loop ----
    const size_t cs = (size_t)2 * BH2;
    for (int t = 0; t < TT; t++) {
        int par = t & 1;

        qgemm_mma<<<dim3(8, 3), 256, G_DSM>>>(dhbh + (size_t)par * BH2, dhbl + (size_t)par * BH2,
                                              wth, wtl, q);
        attend2<<<BB, 256>>>(dh + (size_t)par * BH2, q, attnb[0], attnb[1], attnb[2],
                             enc, cxh, cxl);

        dec_pre<<<dim3(128, 3), 256, RC_DSM>>>(
            cxh, cxl, pvh, pvl,
            dhbh + (size_t)par * BH2, dhbl + (size_t)par * BH2,
            rwh, rwl, dec1_b, dec2_b, dec3_b,
            dcst + 0 * BH2,
            dh + 0 * cs + (size_t)(par ^ 1) * BH2,
            dhbh + 0 * cs + (size_t)(par ^ 1) * BH2, dhbl + 0 * cs + (size_t)(par ^ 1) * BH2,
            gates);

        dec_fin<<<128, 256, E3_DSM>>>(
            dhbh + 0 * cs + (size_t)(par ^ 1) * BH2, dhbl + 0 * cs + (size_t)(par ^ 1) * BH2,
            rwh + OFF_D2I + H2V, rwl + OFF_D2I + H2V, 2 * H2V,
            gates,
            dcst + 1 * BH2,
            dh + 1 * cs + (size_t)(par ^ 1) * BH2,
            dhbh + 1 * cs + (size_t)(par ^ 1) * BH2, dhbl + 1 * cs + (size_t)(par ^ 1) * BH2);

        dec_fin<<<128, 256, E3_DSM>>>(
            dhbh + 1 * cs + (size_t)(par ^ 1) * BH2, dhbl + 1 * cs + (size_t)(par ^ 1) * BH2,
            rwh + OFF_D3I + H2V, rwl + OFF_D3I + H2V, 2 * H2V,
            gates + (size_t)BB * GDV,
            dcst + 2 * BH2,
            dh + 2 * cs + (size_t)(par ^ 1) * BH2,
            dhbh + 2 * cs + (size_t)(par ^ 1) * BH2, dhbl + 2 * cs + (size_t)(par ^ 1) * BH2);

        out_proj<<<BB, 64>>>(dh + 2 * cs + (size_t)(par ^ 1) * BH2, out_W, out_b, out, pvh, pvl, t);
    }
}

// round 17
// speedup vs baseline: 1.1842x; 1.0591x over previous
#include <cuda_runtime.h>
#include <cuda_bf16.h>
#include <cstdint>
#include <cstddef>

// Problem dims
#define BB  128
#define SS  256
#define DD  64
#define HH  512
#define H2V 1024
#define GEV 2048
#define GDV 4096
#define TT  60
#define BSV (BB*SS)      // 32768
#define BHV (BB*HH)      // 65536
#define BH2 (BB*H2V)     // 131072

// ---------------- scratch (device globals; no allocation allowed) -------------
__device__ float g_xg  [2*BSV*GEV];   // gate preactivations [dir][b][s][g]
__device__ float g_h0  [BSV*H2V];     // encoder layer0 output
__device__ float g_enc [BSV*H2V];     // encoder layer1 output
__device__ float g_ec  [2*BHV];       // enc c [dir][b][h]
__device__ float g_dh  [6*BH2];       // dec h fp32 ping-pong [cell][parity][b][h2]
__device__ float g_dc  [3*BH2];       // dec c
__device__ float g_gates[2*BB*GDV];   // partial gates for cells 2,3
__device__ float g_q   [3*BH2];       // attention queries q = W^T h [head][b][1024]

// bf16 split buffers (wbf reused: enc Wih splits early, then WT splits)
__device__ __nv_bfloat16 g_abf_hi[BSV*H2V];
__device__ __nv_bfloat16 g_abf_lo[BSV*H2V];
__device__ __nv_bfloat16 g_wbf_hi[2*GEV*H2V];
__device__ __nv_bfloat16 g_wbf_lo[2*GEV*H2V];

// recurrent weights pre-split (hi/lo)
#define OFF_E0   0ull
#define OFF_E1   2097152ull
#define OFF_D1I  4194304ull
#define OFF_D2I  8650752ull
#define OFF_D3I  17039360ull
#define OFF_D1H  25427968ull
#define OFF_D2H  29622272ull
#define OFF_D3H  33816576ull
#define RW_TOT   38010880ull
__device__ __nv_bfloat16 g_rwh[RW_TOT];
__device__ __nv_bfloat16 g_rwl[RW_TOT];

// recurrent activations bf16 hi/lo
__device__ __nv_bfloat16 g_ehbh[2*2*BHV];   // enc h [par][dir][b][512]
__device__ __nv_bfloat16 g_ehbl[2*2*BHV];
__device__ __nv_bfloat16 g_dhbh[3*2*BH2];   // dec h [cell][par][b][1024]
__device__ __nv_bfloat16 g_dhbl[3*2*BH2];
__device__ __nv_bfloat16 g_cxh [3*BH2];     // ctx [head][b][1024]
__device__ __nv_bfloat16 g_cxl [3*BH2];
__device__ __nv_bfloat16 g_pvh [BB*DD];     // prev y bf16
__device__ __nv_bfloat16 g_pvl [BB*DD];

__device__ __forceinline__ float sigf(float x) { return 1.0f / (1.0f + expf(-x)); }

__device__ __forceinline__ uint32_t smem_u32(const void* p) {
    uint32_t a;
    asm("{ .reg .u64 t; cvta.to.shared.u64 t, %1; cvt.u32.u64 %0, t; }" : "=r"(a) : "l"(p));
    return a;
}

#define MMA4(d, a, b0v, b1v) \
    asm volatile( \
        "mma.sync.aligned.m16n8k16.row.col.f32.bf16.bf16.f32 " \
        "{%0,%1,%2,%3},{%4,%5,%6,%7},{%8,%9},{%0,%1,%2,%3};" \
        : "+f"((d)[0]), "+f"((d)[1]), "+f"((d)[2]), "+f"((d)[3]) \
        : "r"((a)[0]), "r"((a)[1]), "r"((a)[2]), "r"((a)[3]), "r"(b0v), "r"(b1v))

#define LDSM4(r, addr) \
    asm volatile("ldmatrix.sync.aligned.m8n8.x4.shared.b16 {%0,%1,%2,%3},[%4];" \
        : "=r"((r)[0]), "=r"((r)[1]), "=r"((r)[2]), "=r"((r)[3]) : "r"(addr))

#define LDSM4B(r0, r1, r2, r3, addr) \
    asm volatile("ldmatrix.sync.aligned.m8n8.x4.shared.b16 {%0,%1,%2,%3},[%4];" \
        : "=r"(r0), "=r"(r1), "=r"(r2), "=r"(r3) : "r"(addr))

// =====================  batch HMMA bf16-split GEMM (verified R5) =============
#define G_TILE_B 10240
#define G_STG    (4 * G_TILE_B)
#define G_DSM    (2 * G_STG + 128)

__device__ __forceinline__ void gemm_body(
    const __nv_bfloat16* __restrict__ Ahi, const __nv_bfloat16* __restrict__ Alo,
    const __nv_bfloat16* __restrict__ Whi, const __nv_bfloat16* __restrict__ Wlo,
    const float* __restrict__ bias, float* __restrict__ C, int N, int K,
    int bm, int bn, char* dsm)
{
    const int tid = threadIdx.x, lane = tid & 31, wid = tid >> 5;
    const int wr = wid >> 1, wc = wid & 1;
    const uint32_t sbase = (smem_u32(dsm) + 127u) & ~127u;
    const int nch = K >> 5;

    float acc[2][8][4];
#pragma unroll
    for (int mi = 0; mi < 2; mi++)
#pragma unroll
        for (int ni = 0; ni < 8; ni++)
#pragma unroll
            for (int q = 0; q < 4; q++) acc[mi][ni][q] = 0.0f;

    auto load = [&](int c, int st) {
#pragma unroll
        for (int q = 0; q < 8; q++) {
            int id = q * 256 + tid;
            int t  = id >> 9;
            int r  = (id >> 2) & 127;
            int sg = id & 3;
            const __nv_bfloat16* basep = (t == 0 ? Ahi : t == 1 ? Alo : t == 2 ? Whi : Wlo);
            int grow = (t < 2 ? bm : bn) + r;
            const __nv_bfloat16* src = basep + (size_t)grow * K + c * 32 + sg * 8;
            uint32_t dst = sbase + st * G_STG + t * G_TILE_B + r * 80 + sg * 16;
            asm volatile("cp.async.cg.shared.global [%0], [%1], 16;" :: "r"(dst), "l"(src));
        }
        asm volatile("cp.async.commit_group;" ::: "memory");
    };

    load(0, 0);

    for (int c = 0; c < nch; c++) {
        if (c + 1 < nch) {
            load(c + 1, (c + 1) & 1);
            asm volatile("cp.async.wait_group 1;" ::: "memory");
        } else {
            asm volatile("cp.async.wait_group 0;" ::: "memory");
        }
        __syncthreads();

        const uint32_t stb = sbase + (c & 1) * G_STG;
        const uint32_t aB[2] = { stb, stb + G_TILE_B };
        const uint32_t wB[2] = { stb + 2 * G_TILE_B, stb + 3 * G_TILE_B };
        const int arow = wr * 32 + (lane & 15);
        const int wrow = wc * 64 + (lane & 15);
        const int cc   = (lane >> 4) * 16;

#pragma unroll
        for (int ks = 0; ks < 2; ks++) {
            uint32_t afr[2][2][4];
#pragma unroll
            for (int s = 0; s < 2; s++)
#pragma unroll
                for (int mi = 0; mi < 2; mi++) {
                    uint32_t ad = aB[s] + (uint32_t)(arow + mi * 16) * 80 + ks * 32 + cc;
                    LDSM4(afr[s][mi], ad);
                }
#pragma unroll
            for (int wsp = 0; wsp < 2; wsp++) {
#pragma unroll
                for (int nb = 0; nb < 4; nb++) {
                    uint32_t r0, r1, r2, r3;
                    uint32_t bd = wB[wsp] + (uint32_t)(wrow + nb * 16) * 80 + ks * 32 + cc;
                    LDSM4B(r0, r1, r2, r3, bd);
#pragma unroll
                    for (int mi = 0; mi < 2; mi++) {
                        MMA4(acc[mi][nb * 2],     afr[0][mi], r0, r2);
                        MMA4(acc[mi][nb * 2 + 1], afr[0][mi], r1, r3);
                        if (wsp == 0) {
                            MMA4(acc[mi][nb * 2],     afr[1][mi], r0, r2);
                            MMA4(acc[mi][nb * 2 + 1], afr[1][mi], r1, r3);
                        }
                    }
                }
            }
        }
        __syncthreads();
    }

#pragma unroll
    for (int mi = 0; mi < 2; mi++) {
#pragma unroll
        for (int ni = 0; ni < 8; ni++) {
            int r0 = bm + wr * 32 + mi * 16 + (lane >> 2);
            int c0 = bn + wc * 64 + ni * 8 + (lane & 3) * 2;
            float b0v = bias ? bias[c0] : 0.0f;
            float b1v = bias ? bias[c0 + 1] : 0.0f;
            float2 v0 = { acc[mi][ni][0] + b0v, acc[mi][ni][1] + b1v };
            float2 v1 = { acc[mi][ni][2] + b0v, acc[mi][ni][3] + b1v };
            *(float2*)&C[(size_t)r0 * N + c0]       = v0;
            *(float2*)&C[(size_t)(r0 + 8) * N + c0] = v1;
        }
    }
}

__global__ __launch_bounds__(256) void gemm_mma(
    const __nv_bfloat16* __restrict__ Ahi, const __nv_bfloat16* __restrict__ Alo,
    const __nv_bfloat16* __restrict__ Whi, const __nv_bfloat16* __restrict__ Wlo,
    const float* __restrict__ bias, float* __restrict__ C, int N, int K)
{
    extern __shared__ char dsm[];
    gemm_body(Ahi, Alo, Whi, Wlo, bias, C, N, K, blockIdx.y * 128, blockIdx.x * 128, dsm);
}

// q[head] = h[head] @ WT[head]
__global__ __launch_bounds__(256) void qgemm_mma(
    const __nv_bfloat16* __restrict__ hbh, const __nv_bfloat16* __restrict__ hbl,
    const __nv_bfloat16* __restrict__ wth, const __nv_bfloat16* __restrict__ wtl,
    float* __restrict__ q)
{
    extern __shared__ char dsm[];
    const int head = blockIdx.y;
    const size_t cs = (size_t)2 * BH2;
    gemm_body(hbh + (size_t)head * cs, hbl + (size_t)head * cs,
              wth + (size_t)head * H2V * H2V, wtl + (size_t)head * H2V * H2V,
              nullptr, q + (size_t)head * BH2, H2V, H2V,
              0, blockIdx.x * 128, dsm);
}

// fp32 -> bf16 hi/lo split
__global__ void split_bf16(const float* __restrict__ s, __nv_bfloat16* __restrict__ hi,
                           __nv_bfloat16* __restrict__ lo, long n)
{
    long stride = (long)gridDim.x * blockDim.x;
    for (long i = blockIdx.x * (long)blockDim.x + threadIdx.x; i < n; i += stride) {
        float v = s[i];
        __nv_bfloat16 h = __float2bfloat16(v);
        hi[i] = h;
        lo[i] = __float2bfloat16(v - __bfloat162float(h));
    }
}

// transpose + split: WT[e][d] = W[d][e], 1024x1024, bf16 hi/lo
__global__ __launch_bounds__(256) void transpose_split(
    const float* __restrict__ W, __nv_bfloat16* __restrict__ hi, __nv_bfloat16* __restrict__ lo)
{
    __shared__ float tile[32][33];
    const int bx = blockIdx.x * 32, by = blockIdx.y * 32;
    const int tx = threadIdx.x & 31, ty = threadIdx.x >> 5;
#pragma unroll
    for (int i = 0; i < 32; i += 8)
        tile[ty + i][tx] = W[(size_t)(bx + ty + i) * H2V + by + tx];
    __syncthreads();
#pragma unroll
    for (int i = 0; i < 32; i += 8) {
        float v = tile[tx][ty + i];
        size_t idx = (size_t)(by + ty + i) * H2V + bx + tx;
        __nv_bfloat16 h = __float2bfloat16(v);
        hi[idx] = h;
        lo[idx] = __float2bfloat16(v - __bfloat162float(h));
    }
}

// =====================  HMMA recurrent cell machinery ========================
// Block tile M=128 (batch) x N=32 (4 gates x 8 units); 8 warps of 16x32.
// K chunks of 64. 144B rows (conflict-free ldmatrix).
#define RC_ATILE 18432                 // 128*144
#define RC_WOFF  36864                 // 2*RC_ATILE
#define RC_WTILE 4608                  // 32*144
#define RC_STG   46080
// dec_pre: 2-stage (2 CTAs/SM at 109.5KB; grid 384 needs the occupancy)
#define RC_GS_OFF (2 * RC_STG)         // 92160
#define RC_DSM   (RC_GS_OFF + 128 * 34 * 4)   // 109568
// 3-stage (encoder + dec_fin: single-wave grids, latency-bound)
#define E3_GS_OFF (3 * RC_STG)         // 138240
#define E3_DSM   (E3_GS_OFF + 128 * 34 * 4)   // 155648

struct Seg {
    const __nv_bfloat16 *Ah, *Al, *Wh, *Wl;
    int lda, ldw, nch;   // nch in 64-wide chunks
};

__device__ __forceinline__ void rc_load64(const Seg& s, int kc, uint32_t stb,
                                          int tid, int ubase, int GST)
{
#pragma unroll
    for (int q = 0; q < 10; q++) {
        int id = q * 256 + tid;      // 0..2559
        uint32_t dst; const __nv_bfloat16* src;
        if (id < 2048) {             // A: 2 tiles x 128 rows x 8 segs
            int t = id >> 10, r = (id >> 3) & 127, sg = id & 7;
            src = (t ? s.Al : s.Ah) + (size_t)r * s.lda + kc + sg * 8;
            dst = stb + t * RC_ATILE + r * 144 + sg * 16;
        } else {                     // W: 2 tiles x 32 rows x 8 segs
            int id2 = id - 2048;     // 0..511
            int t = id2 >> 8, r = (id2 >> 3) & 31, sg = id2 & 7;
            int grow = (r >> 3) * GST + ubase + (r & 7);
            src = (t ? s.Wl : s.Wh) + (size_t)grow * s.ldw + kc + sg * 8;
            dst = stb + RC_WOFF + t * RC_WTILE + r * 144 + sg * 16;
        }
        asm volatile("cp.async.cg.shared.global [%0], [%1], 16;" :: "r"(dst), "l"(src));
    }
    asm volatile("cp.async.commit_group;" ::: "memory");
}

__device__ __forceinline__ void rc_consume64(uint32_t stb, int wid, int lane,
                                             float (*acc)[4])
{
    const uint32_t cc   = (lane >> 4) * 16;
    const uint32_t arow = wid * 16 + (lane & 15);
    const uint32_t wrow = (lane & 15);
#pragma unroll
    for (int ks = 0; ks < 4; ks++) {
        uint32_t ah[4], al[4];
        LDSM4(ah, stb + arow * 144 + ks * 32 + cc);
        LDSM4(al, stb + RC_ATILE + arow * 144 + ks * 32 + cc);
        uint32_t b0,b1,b2,b3,b4,b5,b6,b7;
        LDSM4B(b0,b1,b2,b3, stb + RC_WOFF + wrow * 144 + ks * 32 + cc);
        LDSM4B(b4,b5,b6,b7, stb + RC_WOFF + (wrow + 16) * 144 + ks * 32 + cc);
        uint32_t l0,l1,l2,l3,l4,l5,l6,l7;
        LDSM4B(l0,l1,l2,l3, stb + RC_WOFF + RC_WTILE + wrow * 144 + ks * 32 + cc);
        LDSM4B(l4,l5,l6,l7, stb + RC_WOFF + RC_WTILE + (wrow + 16) * 144 + ks * 32 + cc);
        MMA4(acc[0], ah, b0, b2); MMA4(acc[0], al, b0, b2); MMA4(acc[0], ah, l0, l2);
        MMA4(acc[1], ah, b1, b3); MMA4(acc[1], al, b1, b3); MMA4(acc[1], ah, l1, l3);
        MMA4(acc[2], ah, b4, b6); MMA4(acc[2], al, b4, b6); MMA4(acc[2], ah, l4, l6);
        MMA4(acc[3], ah, b5, b7); MMA4(acc[3], al, b5, b7); MMA4(acc[3], ah, l5, l7);
    }
}

__device__ __forceinline__ void rc_epilogue_to_smem(float (*gs)[34], float (*acc)[4],
                                                    int wid, int lane)
{
#pragma unroll
    for (int nt = 0; nt < 4; nt++) {
        int r0 = wid * 16 + (lane >> 2);
        int c0 = nt * 8 + (lane & 3) * 2;
        gs[r0][c0]     = acc[nt][0];
        gs[r0][c0 + 1] = acc[nt][1];
        gs[r0 + 8][c0]     = acc[nt][2];
        gs[r0 + 8][c0 + 1] = acc[nt][3];
    }
}

// 2-stage pipeline driver over a segment list (dec_pre)
__device__ __forceinline__ void rc_run(const Seg* segs, int total, uint32_t sb,
                                       int tid, int wid, int lane, int ubase, int GST,
                                       float (*acc)[4])
{
    int si = 0, kc = 0;
    rc_load64(segs[0], 0, sb, tid, ubase, GST);
    for (int ci = 0; ci < total; ci++) {
        int nsi = si, nkc = kc + 64;
        if (nkc >= segs[nsi].nch * 64) { nsi++; nkc = 0; }
        if (ci + 1 < total) {
            rc_load64(segs[nsi], nkc, sb + ((ci + 1) & 1) * RC_STG, tid, ubase, GST);
            asm volatile("cp.async.wait_group 1;" ::: "memory");
        } else {
            asm volatile("cp.async.wait_group 0;" ::: "memory");
        }
        __syncthreads();
        rc_consume64(sb + (ci & 1) * RC_STG, wid, lane, acc);
        __syncthreads();
        si = nsi; kc = nkc;
    }
}

// 3-stage single-segment driver (encoder step, dec_fin)
__device__ __forceinline__ void rc_run3(const Seg& s, int total, uint32_t sb,
                                        int tid, int wid, int lane, int ubase, int GST,
                                        float (*acc)[4])
{
    rc_load64(s, 0, sb, tid, ubase, GST);
    if (total > 1) rc_load64(s, 64, sb + RC_STG, tid, ubase, GST);
    for (int ci = 0; ci < total; ci++) {
        if (ci + 2 < total)
            rc_load64(s, (ci + 2) * 64, sb + ((ci + 2) % 3) * RC_STG, tid, ubase, GST);
        int inflight = total - 1 - ci; if (inflight > 2) inflight = 2;
        if (inflight >= 2)      asm volatile("cp.async.wait_group 2;" ::: "memory");
        else if (inflight == 1) asm volatile("cp.async.wait_group 1;" ::: "memory");
        else                    asm volatile("cp.async.wait_group 0;" ::: "memory");
        __syncthreads();
        rc_consume64(sb + (ci % 3) * RC_STG, wid, lane, acc);
        __syncthreads();
    }
}

// ---------------- encoder recurrent step (HMMA, 3-stage pipeline) -------------
__global__ __launch_bounds__(256) void enc_step_mma(
    const __nv_bfloat16* __restrict__ hh, const __nv_bfloat16* __restrict__ hl,
    const __nv_bfloat16* __restrict__ Wh, const __nv_bfloat16* __restrict__ Wl,
    const float* __restrict__ xg, float* __restrict__ cst,
    __nv_bfloat16* __restrict__ hho, __nv_bfloat16* __restrict__ hlo,
    float* __restrict__ hs, int t)
{
    extern __shared__ char dsm[];
    const int tid = threadIdx.x, lane = tid & 31, wid = tid >> 5;
    const int dir = blockIdx.y, ubase = blockIdx.x * 8;
    const int td = dir ? (SS - 1 - t) : t;
    const uint32_t sb = smem_u32(dsm);
    float (*gs)[34] = (float (*)[34])(dsm + E3_GS_OFF);

    Seg s = { hh + (size_t)dir * BHV, hl + (size_t)dir * BHV,
              Wh + (size_t)dir * GEV * HH, Wl + (size_t)dir * GEV * HH,
              HH, HH, 8 };

    float acc[4][4];
#pragma unroll
    for (int nt = 0; nt < 4; nt++)
#pragma unroll
        for (int q = 0; q < 4; q++) acc[nt][q] = 0.0f;

    rc_run3(s, 8, sb, tid, wid, lane, ubase, HH, acc);

    rc_epilogue_to_smem(gs, acc, wid, lane);
    __syncthreads();

    const float* xgp = xg + (size_t)dir * BSV * GEV;
    float* cp = cst + (size_t)dir * BHV;
#pragma unroll
    for (int k = 0; k < 4; k++) {
        int idx = k * 256 + tid;
        int b = idx >> 3, u = idx & 7;
        int uu = ubase + u;
        size_t xrow = ((size_t)b * SS + td) * GEV;
        float gi = gs[b][u]      + xgp[xrow + uu];
        float gf = gs[b][8 + u]  + xgp[xrow + 512 + uu];
        float gg = gs[b][16 + u] + xgp[xrow + 1024 + uu];
        float go = gs[b][24 + u] + xgp[xrow + 1536 + uu];
        int hidx = b * HH + uu;
        float c = sigf(gf) * cp[hidx] + sigf(gi) * tanhf(gg);
        float h = sigf(go) * tanhf(c);
        cp[hidx] = c;
        hs[((size_t)b * SS + td) * H2V + dir * HH + uu] = h;
        __nv_bfloat16 hb = __float2bfloat16(h);
        hho[(size_t)dir * BHV + hidx] = hb;
        hlo[(size_t)dir * BHV + hidx] = __float2bfloat16(h - __bfloat162float(hb));
    }
}

// ---------------- decoder: parallel pre-pass (cell1 full + cells 2,3 partial) -
__global__ __launch_bounds__(256) void dec_pre(
    const __nv_bfloat16* __restrict__ cxh, const __nv_bfloat16* __restrict__ cxl,
    const __nv_bfloat16* __restrict__ pvh, const __nv_bfloat16* __restrict__ pvl,
    const __nv_bfloat16* __restrict__ hph, const __nv_bfloat16* __restrict__ hpl,
    const __nv_bfloat16* __restrict__ rwh, const __nv_bfloat16* __restrict__ rwl,
    const float* __restrict__ b1, const float* __restrict__ b2, const float* __restrict__ b3,
    float* __restrict__ cst1, float* __restrict__ h1fo,
    __nv_bfloat16* __restrict__ h1ho, __nv_bfloat16* __restrict__ h1lo,
    float* __restrict__ gates)
{
    extern __shared__ char dsm[];
    const int tid = threadIdx.x, lane = tid & 31, wid = tid >> 5;
    const int ubase = blockIdx.x * 8;
    const int c = blockIdx.y;
    const uint32_t sb = smem_u32(dsm);
    float (*gs)[34] = (float (*)[34])(dsm + RC_GS_OFF);
    const size_t cs = (size_t)2 * BH2;

    const unsigned long long offI = c == 0 ? OFF_D1I : (c == 1 ? OFF_D2I : OFF_D3I);
    const unsigned long long offH = c == 0 ? OFF_D1H : (c == 1 ? OFF_D2H : OFF_D3H);
    const int ldih = c == 0 ? (H2V + DD) : (2 * H2V);
    const float* bias = c == 0 ? b1 : (c == 1 ? b2 : b3);

    Seg segs[3];
    int total;
    segs[0] = { cxh + (size_t)c * BH2, cxl + (size_t)c * BH2,
                rwh + offI, rwl + offI, H2V, ldih, 16 };
    if (c == 0) {
        segs[1] = { pvh, pvl, rwh + offI + H2V, rwl + offI + H2V, DD, ldih, 1 };
        segs[2] = { hph, hpl, rwh + offH, rwl + offH, H2V, H2V, 16 };
        total = 33;
    } else {
        segs[1] = { hph + (size_t)c * cs, hpl + (size_t)c * cs,
                    rwh + offH, rwl + offH, H2V, H2V, 16 };
        total = 32;
    }

    float acc[4][4];
#pragma unroll
    for (int nt = 0; nt < 4; nt++)
#pragma unroll
        for (int q = 0; q < 4; q++) acc[nt][q] = 0.0f;

    rc_run(segs, total, sb, tid, wid, lane, ubase, H2V, acc);

    rc_epilogue_to_smem(gs, acc, wid, lane);
    __syncthreads();

    if (c == 0) {
#pragma unroll
        for (int k = 0; k < 4; k++) {
            int idx = k * 256 + tid;
            int b = idx >> 3, u = idx & 7;
            int uu = ubase + u;
            float gi = gs[b][u]      + bias[uu];
            float gf = gs[b][8 + u]  + bias[1024 + uu];
            float gg = gs[b][16 + u] + bias[2048 + uu];
            float go = gs[b][24 + u] + bias[3072 + uu];
            int hidx = b * H2V + uu;
            float cc = sigf(gf) * cst1[hidx] + sigf(gi) * tanhf(gg);
            float h = sigf(go) * tanhf(cc);
            cst1[hidx] = cc;
            h1fo[hidx] = h;
            __nv_bfloat16 hb = __float2bfloat16(h);
            h1ho[hidx] = hb;
            h1lo[hidx] = __float2bfloat16(h - __bfloat162float(hb));
        }
    } else {
        float* gp = gates + (size_t)(c - 1) * BB * GDV;
#pragma unroll
        for (int k = 0; k < 4; k++) {
            int idx = k * 256 + tid;
            int b = idx >> 3, u = idx & 7;
            int uu = ubase + u;
            gp[(size_t)b * GDV + uu]        = gs[b][u]      + bias[uu];
            gp[(size_t)b * GDV + 1024 + uu] = gs[b][8 + u]  + bias[1024 + uu];
            gp[(size_t)b * GDV + 2048 + uu] = gs[b][16 + u] + bias[2048 + uu];
            gp[(size_t)b * GDV + 3072 + uu] = gs[b][24 + u] + bias[3072 + uu];
        }
    }
}

// ---------------- decoder: finish cell (3-stage; single wave grid=128) --------
__global__ __launch_bounds__(256) void dec_fin(
    const __nv_bfloat16* __restrict__ ih, const __nv_bfloat16* __restrict__ il,
    const __nv_bfloat16* __restrict__ Wh, const __nv_bfloat16* __restrict__ Wl,
    int ldw,
    const float* __restrict__ gpart,
    float* __restrict__ cst, float* __restrict__ hfo,
    __nv_bfloat16* __restrict__ hho, __nv_bfloat16* __restrict__ hlo)
{
    extern __shared__ char dsm[];
    const int tid = threadIdx.x, lane = tid & 31, wid = tid >> 5;
    const int ubase = blockIdx.x * 8;
    const uint32_t sb = smem_u32(dsm);
    float (*gs)[34] = (float (*)[34])(dsm + E3_GS_OFF);

    Seg s = { ih, il, Wh, Wl, H2V, ldw, 16 };

    float acc[4][4];
#pragma unroll
    for (int nt = 0; nt < 4; nt++)
#pragma unroll
        for (int q = 0; q < 4; q++) acc[nt][q] = 0.0f;

    rc_run3(s, 16, sb, tid, wid, lane, ubase, H2V, acc);

    rc_epilogue_to_smem(gs, acc, wid, lane);
    __syncthreads();

#pragma unroll
    for (int k = 0; k < 4; k++) {
        int idx = k * 256 + tid;
        int b = idx >> 3, u = idx & 7;
        int uu = ubase + u;
        const float* gp = gpart + (size_t)b * GDV;
        float gi = gs[b][u]      + gp[uu];
        float gf = gs[b][8 + u]  + gp[1024 + uu];
        float gg = gs[b][16 + u] + gp[2048 + uu];
        float go = gs[b][24 + u] + gp[3072 + uu];
        int hidx = b * H2V + uu;
        float cc = sigf(gf) * cst[hidx] + sigf(gi) * tanhf(gg);
        float h = sigf(go) * tanhf(cc);
        cst[hidx] = cc;
        hfo[hidx] = h;
        __nv_bfloat16 hb = __float2bfloat16(h);
        hho[hidx] = hb;
        hlo[hidx] = __float2bfloat16(h - __bfloat162float(hb));
    }
}

// ---------------- q-based fused 3-head attention + folded out_proj ------------
// Per step t: block b first emits y_{t-1}[b] = h3_{t-1}[b]·outW^T + outb (and
// bf16 prev feedback), then does the unchanged attention work. do_y=0 at t=0.
__global__ __launch_bounds__(256) void attend2(
    const float* __restrict__ dh,
    const float* __restrict__ q,
    const float* __restrict__ ab0, const float* __restrict__ ab1, const float* __restrict__ ab2,
    const float* __restrict__ enc,
    __nv_bfloat16* __restrict__ cxh, __nv_bfloat16* __restrict__ cxl,
    const float* __restrict__ h3p,   // h3 from step t-1 (same parity base)
    const float* __restrict__ outW, const float* __restrict__ outb,
    float* __restrict__ y,
    __nv_bfloat16* __restrict__ pvh, __nv_bfloat16* __restrict__ pvl,
    int tprev, int do_y)
{
    const int b = blockIdx.x, tid = threadIdx.x, lane = tid & 31, wid = tid >> 5;
    __shared__ float sa[3][SS];
    __shared__ float red[3][8];
    __shared__ float shb[3];
    __shared__ float redm[3][8];
    __shared__ float reds[3][8];
    __shared__ float sh3[H2V];

    // ---- folded out_proj: warp-per-row dot, same pattern as score pass ----
    if (do_y) {
        for (int i = tid; i < H2V; i += 256)
            sh3[i] = h3p[(size_t)b * H2V + i];
        __syncthreads();
#pragma unroll
        for (int d8 = 0; d8 < 8; d8++) {
            int d = wid * 8 + d8;
            const float* wr = outW + (size_t)d * H2V + lane * 4;
            float acc = 0.0f;
#pragma unroll
            for (int k = 0; k < 8; k++) {
                float4 wv = *(const float4*)(wr + k * 128);
                int kk = k * 128 + lane * 4;
                acc += wv.x * sh3[kk] + wv.y * sh3[kk + 1]
                     + wv.z * sh3[kk + 2] + wv.w * sh3[kk + 3];
            }
#pragma unroll
            for (int off = 16; off; off >>= 1)
                acc += __shfl_xor_sync(0xffffffffu, acc, off);
            if (lane == 0) {
                float v = acc + outb[d];
                y[((size_t)b * TT + tprev) * DD + d] = v;
                __nv_bfloat16 hb = __float2bfloat16(v);
                pvh[b * DD + d] = hb;
                pvl[b * DD + d] = __float2bfloat16(v - __bfloat162float(hb));
            }
        }
    }

    // ---- fused hb phase: all 3 heads in one pass ----
    {
        float p0 = 0.0f, p1 = 0.0f, p2 = 0.0f;
        const float* h0p = dh + (size_t)0 * 2 * BH2 + (size_t)b * H2V;
        const float* h1p = dh + (size_t)1 * 2 * BH2 + (size_t)b * H2V;
        const float* h2p = dh + (size_t)2 * 2 * BH2 + (size_t)b * H2V;
        for (int d = tid; d < H2V; d += 256) {
            p0 += h0p[d] * ab0[d];
            p1 += h1p[d] * ab1[d];
            p2 += h2p[d] * ab2[d];
        }
#pragma unroll
        for (int off = 16; off; off >>= 1) {
            p0 += __shfl_xor_sync(0xffffffffu, p0, off);
            p1 += __shfl_xor_sync(0xffffffffu, p1, off);
            p2 += __shfl_xor_sync(0xffffffffu, p2, off);
        }
        if (lane == 0) { red[0][wid] = p0; red[1][wid] = p1; red[2][wid] = p2; }
        __syncthreads();
        if (tid < 3) {
            float s = 0.0f;
#pragma unroll
            for (int i = 0; i < 8; i++) s += red[tid][i];
            shb[tid] = s;
        }
        __syncthreads();
    }

    float4 qr[3][8];
#pragma unroll
    for (int hd = 0; hd < 3; hd++)
#pragma unroll
        for (int k = 0; k < 8; k++)
            qr[hd][k] = *(const float4*)&q[(size_t)hd * BH2 + (size_t)b * H2V + k * 128 + lane * 4];

    const float* eb = enc + (size_t)b * SS * H2V;
    for (int s = wid * 32; s < wid * 32 + 32; s++) {
        const float* er = eb + (size_t)s * H2V + lane * 4;
        float a0 = 0.0f, a1 = 0.0f, a2 = 0.0f;
#pragma unroll
        for (int k = 0; k < 8; k++) {
            float4 ev = *(const float4*)(er + k * 128);
            a0 += ev.x * qr[0][k].x + ev.y * qr[0][k].y + ev.z * qr[0][k].z + ev.w * qr[0][k].w;
            a1 += ev.x * qr[1][k].x + ev.y * qr[1][k].y + ev.z * qr[1][k].z + ev.w * qr[1][k].w;
            a2 += ev.x * qr[2][k].x + ev.y * qr[2][k].y + ev.z * qr[2][k].z + ev.w * qr[2][k].w;
        }
#pragma unroll
        for (int off = 16; off; off >>= 1) {
            a0 += __shfl_xor_sync(0xffffffffu, a0, off);
            a1 += __shfl_xor_sync(0xffffffffu, a1, off);
            a2 += __shfl_xor_sync(0xffffffffu, a2, off);
        }
        if (lane == 0) {
            sa[0][s] = a0 + shb[0];
            sa[1][s] = a1 + shb[1];
            sa[2][s] = a2 + shb[2];
        }
    }
    __syncthreads();

    float ev3[3];
#pragma unroll
    for (int hd = 0; hd < 3; hd++) {
        float m = sa[hd][tid];
#pragma unroll
        for (int off = 16; off; off >>= 1)
            m = fmaxf(m, __shfl_xor_sync(0xffffffffu, m, off));
        if (lane == 0) redm[hd][wid] = m;
    }
    __syncthreads();
#pragma unroll
    for (int hd = 0; hd < 3; hd++) {
        float m = redm[hd][0];
#pragma unroll
        for (int i = 1; i < 8; i++) m = fmaxf(m, redm[hd][i]);
        float e = expf(sa[hd][tid] - m);
        ev3[hd] = e;
        float ssum = e;
#pragma unroll
        for (int off = 16; off; off >>= 1)
            ssum += __shfl_xor_sync(0xffffffffu, ssum, off);
        if (lane == 0) reds[hd][wid] = ssum;
    }
    __syncthreads();
#pragma unroll
    for (int hd = 0; hd < 3; hd++) {
        float tot = reds[hd][0];
#pragma unroll
        for (int i = 1; i < 8; i++) tot += reds[hd][i];
        sa[hd][tid] = ev3[hd] / tot;
    }
    __syncthreads();

    float4 a0 = {0,0,0,0}, a1 = {0,0,0,0}, a2 = {0,0,0,0};
    const float* er = enc + (size_t)b * SS * H2V + tid * 4;
#pragma unroll 4
    for (int s = 0; s < SS; s++) {
        float4 ev4 = *(const float4*)(er + (size_t)s * H2V);
        float w0 = sa[0][s], w1 = sa[1][s], w2 = sa[2][s];
        a0.x += w0 * ev4.x; a0.y += w0 * ev4.y; a0.z += w0 * ev4.z; a0.w += w0 * ev4.w;
        a1.x += w1 * ev4.x; a1.y += w1 * ev4.y; a1.z += w1 * ev4.z; a1.w += w1 * ev4.w;
        a2.x += w2 * ev4.x; a2.y += w2 * ev4.y; a2.z += w2 * ev4.z; a2.w += w2 * ev4.w;
    }
#pragma unroll
    for (int hd = 0; hd < 3; hd++) {
        float4 v = hd == 0 ? a0 : hd == 1 ? a1 : a2;
        size_t base = (size_t)hd * BH2 + (size_t)b * H2V + tid * 4;
        float vv[4] = { v.x, v.y, v.z, v.w };
#pragma unroll
        for (int qd = 0; qd < 4; qd++) {
            __nv_bfloat16 hb = __float2bfloat16(vv[qd]);
            cxh[base + qd] = hb;
            cxl[base + qd] = __float2bfloat16(vv[qd] - __bfloat162float(hb));
        }
    }
}

// ---------------- output projection (final step only) --------------------------
__global__ __launch_bounds__(64) void out_proj(
    const float* __restrict__ h,
    const float* __restrict__ W,
    const float* __restrict__ bias,
    float* __restrict__ y,
    __nv_bfloat16* __restrict__ pvh, __nv_bfloat16* __restrict__ pvl,
    int t)
{
    const int b = blockIdx.x, d = threadIdx.x;
    __shared__ float sh[H2V];
    for (int i = d; i < H2V; i += 64) sh[i] = h[(size_t)b * H2V + i];
    __syncthreads();
    float acc = bias[d];
    const float* wr = W + (size_t)d * H2V;
    for (int k = 0; k < H2V; k += 4) {
        float4 wv = *(const float4*)(wr + k);
        acc += wv.x * sh[k] + wv.y * sh[k + 1] + wv.z * sh[k + 2] + wv.w * sh[k + 3];
    }
    y[((size_t)b * TT + t) * DD + d] = acc;
    __nv_bfloat16 hb = __float2bfloat16(acc);
    pvh[b * DD + d] = hb;
    pvl[b * DD + d] = __float2bfloat16(acc - __bfloat162float(hb));
}

__global__ void set_prev(const float* __restrict__ x,
                         __nv_bfloat16* __restrict__ pvh, __nv_bfloat16* __restrict__ pvl)
{
    int i = blockIdx.x * blockDim.x + threadIdx.x;
    if (i < BB * DD) {
        int b = i / DD, d = i % DD;
        float v = x[((size_t)b * SS + (SS - 1)) * DD + d];
        __nv_bfloat16 hb = __float2bfloat16(v);
        pvh[i] = hb;
        pvl[i] = __float2bfloat16(v - __bfloat162float(hb));
    }
}

// ---------------- host orchestration ------------------------------------------
extern "C" void kernel_launch(void* const* d_in, const int* in_sizes, int n_in,
                              void* d_out, int out_size)
{
    (void)in_sizes; (void)n_in; (void)out_size;
    const float* x        = (const float*)d_in[0];
    const float* enc0_Wih = (const float*)d_in[1];
    const float* enc0_Whh = (const float*)d_in[2];
    const float* enc0_b   = (const float*)d_in[3];
    const float* enc1_Wih = (const float*)d_in[4];
    const float* enc1_Whh = (const float*)d_in[5];
    const float* enc1_b   = (const float*)d_in[6];
    const float* attnW[3] = {(const float*)d_in[7],  (const float*)d_in[9],  (const float*)d_in[11]};
    const float* attnb[3] = {(const float*)d_in[8],  (const float*)d_in[10], (const float*)d_in[12]};
    const float* dec1_Wih = (const float*)d_in[13];
    const float* dec1_Whh = (const float*)d_in[14];
    const float* dec1_b   = (const float*)d_in[15];
    const float* dec2_Wih = (const float*)d_in[16];
    const float* dec2_Whh = (const float*)d_in[17];
    const float* dec2_b   = (const float*)d_in[18];
    const float* dec3_Wih = (const float*)d_in[19];
    const float* dec3_Whh = (const float*)d_in[20];
    const float* dec3_b   = (const float*)d_in[21];
    const float* out_W    = (const float*)d_in[22];
    const float* out_b    = (const float*)d_in[23];
    float* out = (float*)d_out;

    float *xg, *h0, *enc, *ec, *dh, *dcst, *gates, *q;
    __nv_bfloat16 *ah, *al, *wh, *wl, *rwh, *rwl;
    __nv_bfloat16 *ehbh, *ehbl, *dhbh, *dhbl, *cxh, *cxl, *pvh, *pvl;
    cudaGetSymbolAddress((void**)&xg,    g_xg);
    cudaGetSymbolAddress((void**)&h0,    g_h0);
    cudaGetSymbolAddress((void**)&enc,   g_enc);
    cudaGetSymbolAddress((void**)&ec,    g_ec);
    cudaGetSymbolAddress((void**)&dh,    g_dh);
    cudaGetSymbolAddress((void**)&dcst,  g_dc);
    cudaGetSymbolAddress((void**)&gates, g_gates);
    cudaGetSymbolAddress((void**)&q,     g_q);
    cudaGetSymbolAddress((void**)&ah,    g_abf_hi);
    cudaGetSymbolAddress((void**)&al,    g_abf_lo);
    cudaGetSymbolAddress((void**)&wh,    g_wbf_hi);
    cudaGetSymbolAddress((void**)&wl,    g_wbf_lo);
    cudaGetSymbolAddress((void**)&rwh,   g_rwh);
    cudaGetSymbolAddress((void**)&rwl,   g_rwl);
    cudaGetSymbolAddress((void**)&ehbh,  g_ehbh);
    cudaGetSymbolAddress((void**)&ehbl,  g_ehbl);
    cudaGetSymbolAddress((void**)&dhbh,  g_dhbh);
    cudaGetSymbolAddress((void**)&dhbl,  g_dhbl);
    cudaGetSymbolAddress((void**)&cxh,   g_cxh);
    cudaGetSymbolAddress((void**)&cxl,   g_cxl);
    cudaGetSymbolAddress((void**)&pvh,   g_pvh);
    cudaGetSymbolAddress((void**)&pvl,   g_pvl);

    cudaFuncSetAttribute(gemm_mma,     cudaFuncAttributeMaxDynamicSharedMemorySize, G_DSM);
    cudaFuncSetAttribute(qgemm_mma,    cudaFuncAttributeMaxDynamicSharedMemorySize, G_DSM);
    cudaFuncSetAttribute(enc_step_mma, cudaFuncAttributeMaxDynamicSharedMemorySize, E3_DSM);
    cudaFuncSetAttribute(dec_pre,      cudaFuncAttributeMaxDynamicSharedMemorySize, RC_DSM);
    cudaFuncSetAttribute(dec_fin,      cudaFuncAttributeMaxDynamicSharedMemorySize, E3_DSM);

    const size_t dirXG = (size_t)BSV * GEV;

    // ---- pre-split recurrent weights ----
    split_bf16<<<1024, 256>>>(enc0_Whh, rwh + OFF_E0,  rwl + OFF_E0,  2L * GEV * HH);
    split_bf16<<<1024, 256>>>(enc1_Whh, rwh + OFF_E1,  rwl + OFF_E1,  2L * GEV * HH);
    split_bf16<<<1024, 256>>>(dec1_Wih, rwh + OFF_D1I, rwl + OFF_D1I, (long)GDV * (H2V + DD));
    split_bf16<<<1024, 256>>>(dec2_Wih, rwh + OFF_D2I, rwl + OFF_D2I, (long)GDV * 2 * H2V);
    split_bf16<<<1024, 256>>>(dec3_Wih, rwh + OFF_D3I, rwl + OFF_D3I, (long)GDV * 2 * H2V);
    split_bf16<<<1024, 256>>>(dec1_Whh, rwh + OFF_D1H, rwl + OFF_D1H, (long)GDV * H2V);
    split_bf16<<<1024, 256>>>(dec2_Whh, rwh + OFF_D2H, rwl + OFF_D2H, (long)GDV * H2V);
    split_bf16<<<1024, 256>>>(dec3_Whh, rwh + OFF_D3H, rwl + OFF_D3H, (long)GDV * H2V);

    // ---- encoder layer 0 ----
    cudaMemsetAsync(ehbh, 0, sizeof(__nv_bfloat16) * 2 * 2 * BHV);
    cudaMemsetAsync(ehbl, 0, sizeof(__nv_bfloat16) * 2 * 2 * BHV);
    cudaMemsetAsync(ec,   0, sizeof(float) * 2 * BHV);
    split_bf16<<<1024, 256>>>(x, ah, al, (long)BSV * DD);
    split_bf16<<<1024, 256>>>(enc0_Wih, wh, wl, 2L * GEV * DD);
    gemm_mma<<<dim3(GEV / 128, BSV / 128), 256, G_DSM>>>(ah, al, wh, wl, enc0_b, xg, GEV, DD);
    gemm_mma<<<dim3(GEV / 128, BSV / 128), 256, G_DSM>>>(ah, al, wh + (size_t)GEV * DD, wl + (size_t)GEV * DD,
                                                         enc0_b + GEV, xg + dirXG, GEV, DD);
    const size_t eps = (size_t)2 * BHV;
    for (int t = 0; t < SS; t++) {
        int par = t & 1;
        enc_step_mma<<<dim3(64, 2), 256, E3_DSM>>>(
            ehbh + par * eps, ehbl + par * eps,
            rwh + OFF_E0, rwl + OFF_E0,
            xg, ec,
            ehbh + (par ^ 1) * eps, ehbl + (par ^ 1) * eps,
            h0, t);
    }

    // ---- encoder layer 1 ----
    cudaMemsetAsync(ehbh, 0, sizeof(__nv_bfloat16) * 2 * 2 * BHV);
    cudaMemsetAsync(ehbl, 0, sizeof(__nv_bfloat16) * 2 * 2 * BHV);
    cudaMemsetAsync(ec,   0, sizeof(float) * 2 * BHV);
    split_bf16<<<1024, 256>>>(h0, ah, al, (long)BSV * H2V);
    split_bf16<<<1024, 256>>>(enc1_Wih, wh, wl, 2L * GEV * H2V);
    gemm_mma<<<dim3(GEV / 128, BSV / 128), 256, G_DSM>>>(ah, al, wh, wl, enc1_b, xg, GEV, H2V);
    gemm_mma<<<dim3(GEV / 128, BSV / 128), 256, G_DSM>>>(ah, al, wh + (size_t)GEV * H2V, wl + (size_t)GEV * H2V,
                                                         enc1_b + GEV, xg + dirXG, GEV, H2V);
    for (int t = 0; t < SS; t++) {
        int par = t & 1;
        enc_step_mma<<<dim3(64, 2), 256, E3_DSM>>>(
            ehbh + par * eps, ehbl + par * eps,
            rwh + OFF_E1, rwl + OFF_E1,
            xg, ec,
            ehbh + (par ^ 1) * eps, ehbl + (par ^ 1) * eps,
            enc, t);
    }

    // ---- attn WT (transposed, split) ----
    __nv_bfloat16* wth = wh;
    __nv_bfloat16* wtl = wl;
    for (int i = 0; i < 3; i++)
        transpose_split<<<dim3(32, 32), 256>>>(attnW[i],
                                               wth + (size_t)i * H2V * H2V,
                                               wtl + (size_t)i * H2V * H2V);

    // ---- decoder init ----
    cudaMemsetAsync(dh,   0, sizeof(float) * 6 * BH2);
    cudaMemsetAsync(dcst, 0, sizeof(float) * 3 * BH2);
    cudaMemsetAsync(dhbh, 0, sizeof(__nv_bfloat16) * 6 * BH2);
    cudaMemsetAsync(dhbl, 0, sizeof(__nv_bfloat16) * 6 * BH2);
    set_prev<<<32, 256>>>(x, pvh, pvl);

    // ---- decoder loop ----
    const size_t cs = (size_t)2 * BH2;
    for (int t = 0; t < TT; t++) {
        int par = t & 1;

        qgemm_mma<<<dim3(8, 3), 256, G_DSM>>>(dhbh + (size_t)par * BH2, dhbl + (size_t)par * BH2,
                                              wth, wtl, q);

        // attention + folded y_{t-1} projection (writes pv before dec_pre reads it)
        attend2<<<BB, 256>>>(dh + (size_t)par * BH2, q, attnb[0], attnb[1], attnb[2],
                             enc, cxh, cxl,
                             dh + 2 * cs + (size_t)par * BH2,   // h3 from step t-1
                             out_W, out_b, out, pvh, pvl,
                             t - 1, t > 0 ? 1 : 0);

        dec_pre<<<dim3(128, 3), 256, RC_DSM>>>(
            cxh, cxl, pvh, pvl,
            dhbh + (size_t)par * BH2, dhbl + (size_t)par * BH2,
            rwh, rwl, dec1_b, dec2_b, dec3_b,
            dcst + 0 * BH2,
            dh + 0 * cs + (size_t)(par ^ 1) * BH2,
            dhbh + 0 * cs + (size_t)(par ^ 1) * BH2, dhbl + 0 * cs + (size_t)(par ^ 1) * BH2,
            gates);

        dec_fin<<<128, 256, E3_DSM>>>(
            dhbh + 0 * cs + (size_t)(par ^ 1) * BH2, dhbl + 0 * cs + (size_t)(par ^ 1) * BH2,
            rwh + OFF_D2I + H2V, rwl + OFF_D2I + H2V, 2 * H2V,
            gates,
            dcst + 1 * BH2,
            dh + 1 * cs + (size_t)(par ^ 1) * BH2,
            dhbh + 1 * cs + (size_t)(par ^ 1) * BH2, dhbl + 1 * cs + (size_t)(par ^ 1) * BH2);

        dec_fin<<<128, 256, E3_DSM>>>(
            dhbh + 1 * cs + (size_t)(par ^ 1) * BH2, dhbl + 1 * cs + (size_t)(par ^ 1) * BH2,
            rwh + OFF_D3I + H2V, rwl + OFF_D3I + H2V, 2 * H2V,
            gates + (size_t)BB * GDV,
            dcst + 2 * BH2,
            dh + 2 * cs + (size_t)(par ^ 1) * BH2,
            dhbh + 2 * cs + (size_t)(par ^ 1) * BH2, dhbl + 2 * cs + (size_t)(par ^ 1) * BH2);
    }

    // final step's projection (h3 of t=59 at parity (59&1)^1 = 0)
    out_proj<<<BB, 64>>>(dh + 2 * cs + (size_t)(((TT - 1) & 1) ^ 1) * BH2,
                         out_W, out_b, out, pvh, pvl, TT - 1);
}